// round 14
// baseline (speedup 1.0000x reference)
#include <cuda_runtime.h>

typedef unsigned int u32;
typedef unsigned long long u64;

extern "C" __device__ float __nv_expf(float);   // libdevice expf (matches XLA)

#define K_TOP 4096
#define W_IMG 640
#define H_IMG 480
#define NPIX (W_IMG * H_IMG)      // 307200
#define WC 80
#define HC 60
#define NC (WC * HC)              // 4800
#define CH 64
#define CAND_MAX 320000

#define OFF_KPTS  0
#define OFF_MATCH 16384
#define OFF_SCORE 20480
#define OFF_VALID 24576
#define OFF_H     28672
#define OFF_R     643072

__device__ float g_Hs[2 * NPIX];
__device__ float g_FS[2 * NPIX];
__device__ float g_nf[2 * CH * NC];
__device__ u32   g_hist[2][2][65536];
__device__ u32   g_coarse[2][2][256];
__device__ u64   g_prefix[2];
__device__ u32   g_krem[2];
__device__ u32   g_cnt[2];
__device__ u32   g_candn[2][2];
__device__ u64   g_cand[2][2][CAND_MAX];
__device__ u64   g_sel[2][K_TOP];
__device__ int   g_topidx[2][K_TOP];
__device__ float g_desc[2][K_TOP][CH];
__device__ u64   g_rowP[K_TOP];
__device__ u64   g_colP[K_TOP];

__device__ __forceinline__ u32 fkey(float f) {
    u32 u = __float_as_uint(f);
    return (u >> 31) ? ~u : (u | 0x80000000u);
}
__device__ __forceinline__ float unfkey(u32 k) {
    return __uint_as_float((k >> 31) ? (k & 0x7FFFFFFFu) : ~k);
}

__device__ __forceinline__ u32 warp_append(u32* counter, u32 mask) {
    int lane = threadIdx.x & 31;
    u32 ldr = __ffs(mask) - 1;
    u32 base = 0;
    if ((u32)lane == ldr) base = atomicAdd(counter, __popc(mask));
    base = __shfl_sync(mask, base, ldr);
    return base + __popc(mask & ((1u << lane) - 1));
}

// aggregated histogram add for fine+coarse (mask = active lanes)
__device__ __forceinline__ void hist_add(u32* fine, u32* coarse, u32 bin, u32 mask) {
    u32 peers = __match_any_sync(mask, bin);
    if ((u32)(__ffs(peers) - 1) == (threadIdx.x & 31u))
        atomicAdd(&fine[bin], __popc(peers));
    u32 cbin = bin >> 8;
    u32 cpeers = __match_any_sync(mask, cbin);
    if ((u32)(__ffs(cpeers) - 1) == (threadIdx.x & 31u))
        atomicAdd(&coarse[cbin], __popc(cpeers));
}

__global__ void k_init() {
    int i = blockIdx.x * blockDim.x + threadIdx.x;
    int st = blockDim.x * gridDim.x;
    u32* h = &g_hist[0][0][0];
    for (int j = i; j < 2 * 2 * 65536; j += st) h[j] = 0;
    u32* c = &g_coarse[0][0][0];
    for (int j = i; j < 2 * 2 * 256; j += st) c[j] = 0;
    for (int j = i; j < K_TOP; j += st) { g_rowP[j] = 0ull; g_colP[j] = 0ull; }
    if (i < 2) {
        g_prefix[i] = 0ull; g_krem[i] = K_TOP; g_cnt[i] = 0;
        g_candn[i][0] = 0; g_candn[i][1] = 0;
    }
}

// fused: blocks 0..149 softmax+shuffle (XLA column-reduce order),
//        blocks 150..299 feats norm (same association). smem-staged coalesced.
__global__ void k_prep(const float* __restrict__ logits,
                       const float* __restrict__ feats) {
    __shared__ float sm[65 * 65 + 65];
    int blk = blockIdx.x;
    int lane = threadIdx.x & 31, wrp = threadIdx.x >> 5;
    if (blk < 150) {
        int b = blk / 75;
        int cellbase = (blk % 75) * 64;
        const float* p = logits + (size_t)b * 65 * NC + cellbase;
        for (int i = threadIdx.x; i < 65 * 64; i += 256) {
            int ch = i >> 6, cl = i & 63;
            sm[ch * 65 + cl] = p[ch * NC + cl];
        }
        __syncthreads();
        float* out = g_Hs + (size_t)b * NPIX;
        #pragma unroll
        for (int s = 0; s < 8; s++) {
            int cell = wrp * 8 + s;
            float x0 = sm[lane * 65 + cell];
            float x1 = sm[(lane + 32) * 65 + cell];
            float x2 = (lane == 0) ? sm[64 * 65 + cell] : __int_as_float(0xff800000);
            float m = fmaxf(fmaxf(x0, x1), x2);
            #pragma unroll
            for (int off = 16; off > 0; off >>= 1)
                m = fmaxf(m, __shfl_xor_sync(0xFFFFFFFFu, m, off));
            float e0 = __nv_expf(__fsub_rn(x0, m));
            float e1 = __nv_expf(__fsub_rn(x1, m));
            float e2 = __nv_expf(__fsub_rn(x2, m));
            float partial = __fadd_rn(__fadd_rn(e0, e1), e2);
            #pragma unroll
            for (int off = 16; off > 0; off >>= 1)
                partial = __fadd_rn(partial, __shfl_down_sync(0xFFFFFFFFu, partial, off));
            float ssum = __shfl_sync(0xFFFFFFFFu, partial, 0);
            int gcell = cellbase + cell;
            int h = gcell / WC, w = gcell % WC;
            int c0 = lane, c1 = lane + 32;
            out[(h * 8 + (c0 >> 3)) * W_IMG + (w * 8 + (c0 & 7))] = __fdiv_rn(e0, ssum);
            out[(h * 8 + (c1 >> 3)) * W_IMG + (w * 8 + (c1 & 7))] = __fdiv_rn(e1, ssum);
        }
    } else {
        int blk2 = blk - 150;
        int b = blk2 / 75;
        int cellbase = (blk2 % 75) * 64;
        float* nrm = sm + 64 * 65;
        const float* f = feats + (size_t)b * CH * NC + cellbase;
        float* o = g_nf + (size_t)b * CH * NC + cellbase;
        for (int i = threadIdx.x; i < 64 * 64; i += 256) {
            int ch = i >> 6, cl = i & 63;
            sm[ch * 65 + cl] = f[ch * NC + cl];
        }
        __syncthreads();
        #pragma unroll
        for (int s = 0; s < 8; s++) {
            int cell = wrp * 8 + s;
            float x0 = sm[lane * 65 + cell];
            float x1 = sm[(lane + 32) * 65 + cell];
            float partial = __fadd_rn(__fmul_rn(x0, x0), __fmul_rn(x1, x1));
            #pragma unroll
            for (int off = 16; off > 0; off >>= 1)
                partial = __fadd_rn(partial, __shfl_down_sync(0xFFFFFFFFu, partial, off));
            if (lane == 0) nrm[cell] = fmaxf(__fsqrt_rn(partial), 1e-12f);
        }
        __syncthreads();
        for (int i = threadIdx.x; i < 64 * 64; i += 256) {
            int ch = i >> 6, cl = i & 63;
            o[ch * NC + cl] = __fdiv_rn(sm[ch * 65 + cl], nrm[cl]);
        }
    }
}

// 5x5 NMS (smem-tiled) + bilinear reliability + level-0 fine+coarse hist
__global__ void k_nms(const float* __restrict__ heatmap, float* __restrict__ dout) {
    __shared__ float tile[5][324];
    int tid = threadIdx.x;                       // 320 threads
    int gid = blockIdx.x * 320 + tid;            // exact: 2*NPIX (1920 blocks)
    int b = gid / NPIX, p = gid % NPIX;
    int oy = p / W_IMG;
    int xbase = p % W_IMG - tid;                 // 0 or 320 (strip base)
    const float* Hs = g_Hs + (size_t)b * NPIX;
    for (int i = tid; i < 5 * 324; i += 320) {
        int rr = i / 324, cc = i % 324;
        int row = oy - 2 + rr, col = xbase - 2 + cc;
        float v = __int_as_float(0xff800000);
        if ((unsigned)row < H_IMG && (unsigned)col < W_IMG)
            v = Hs[row * W_IMG + col];
        tile[rr][cc] = v;
    }
    __syncthreads();
    int ox = xbase + tid;

    float sy = __fsub_rn(__fmul_rn(__fadd_rn((float)oy, 0.5f), 0.125f), 0.5f);
    float sx = __fsub_rn(__fmul_rn(__fadd_rn((float)ox, 0.5f), 0.125f), 0.5f);
    int iy0 = (int)floorf(sy);
    int ix0 = (int)floorf(sx);
    float fy = __fsub_rn(sy, (float)iy0);
    float fx = __fsub_rn(sx, (float)ix0);
    int y0 = iy0 < 0 ? 0 : iy0;
    int y1 = iy0 >= HC - 1 ? HC - 1 : iy0 + 1;
    int x0 = ix0 < 0 ? 0 : ix0;
    int x1 = ix0 >= WC - 1 ? WC - 1 : ix0 + 1;
    float wy0 = iy0 < 0 ? 0.f : (iy0 >= HC - 1 ? 1.f : __fsub_rn(1.f, fy));
    float wy1 = iy0 < 0 ? 1.f : (iy0 >= HC - 1 ? 0.f : fy);
    float wx0 = ix0 < 0 ? 0.f : (ix0 >= WC - 1 ? 1.f : __fsub_rn(1.f, fx));
    float wx1 = ix0 < 0 ? 1.f : (ix0 >= WC - 1 ? 0.f : fx);
    const float* hm = heatmap + (size_t)b * NC;
    float t0 = __fmaf_rn(wx1, hm[y0 * WC + x1], __fmul_rn(wx0, hm[y0 * WC + x0]));
    float t1 = __fmaf_rn(wx1, hm[y1 * WC + x1], __fmul_rn(wx0, hm[y1 * WC + x0]));
    float rel = __fmaf_rn(wy1, t1, __fmul_rn(wy0, t0));

    float x = tile[2][tid + 2];
    float lm = x;
    #pragma unroll
    for (int dy = 0; dy < 5; dy++)
        #pragma unroll
        for (int dx = 0; dx < 5; dx++)
            lm = fmaxf(lm, tile[dy][tid + dx]);
    float fs = (x == lm) ? __fmul_rn(x, rel) : 0.f;
    if (fs == 0.f) fs = 0.f;   // canonicalize -0
    g_FS[gid] = fs;
    dout[OFF_H + gid] = fs;
    dout[OFF_R + gid] = rel;

    u32 bin = fkey(fs) >> 16;
    hist_add(g_hist[0][b], g_coarse[0][b], bin, 0xFFFFFFFFu);
}

// threshold scan: parallel suffix-sum pick (identical integer results)
template <int L>
__global__ void k_scan() {
    int b = blockIdx.x;
    __shared__ u32 bufA[256], bufB[256];
    __shared__ int csel;
    __shared__ u32 krem2s;
    int t = threadIdx.x;
    u32 krem = g_krem[b];

    bufA[t] = g_coarse[L][b][t];
    __syncthreads();
    u32* cur = bufA; u32* nxt = bufB;
    #pragma unroll
    for (int off = 1; off < 256; off <<= 1) {
        u32 v = cur[t] + ((t + off < 256) ? cur[t + off] : 0u);
        __syncthreads();
        nxt[t] = v;
        __syncthreads();
        u32* tmp = cur; cur = nxt; nxt = tmp;
    }
    u32 sufN = (t == 255) ? 0u : cur[t + 1];
    if (cur[t] >= krem && sufN < krem) { csel = t; krem2s = krem - sufN; }
    __syncthreads();
    int cs = csel;
    u32 krem2 = krem2s;
    __syncthreads();

    bufA[t] = g_hist[L][b][cs * 256 + t];
    __syncthreads();
    cur = bufA; nxt = bufB;
    #pragma unroll
    for (int off = 1; off < 256; off <<= 1) {
        u32 v = cur[t] + ((t + off < 256) ? cur[t + off] : 0u);
        __syncthreads();
        nxt[t] = v;
        __syncthreads();
        u32* tmp = cur; cur = nxt; nxt = tmp;
    }
    u32 sufNf = (t == 255) ? 0u : cur[t + 1];
    if (cur[t] >= krem2 && sufNf < krem2) {
        g_krem[b] = krem2 - sufNf;
        g_prefix[b] = (g_prefix[b] << 16) | (u64)(u32)(cs * 256 + t);
    }
}

// full pass: definite -> g_sel; threshold-bin -> cand[0] + level-1 fine+coarse
__global__ void k_sel0() {
    int gid = blockIdx.x * blockDim.x + threadIdx.x;   // exact: 2*NPIX
    int b = gid / NPIX;
    u32 i = gid % NPIX;
    u64 key = ((u64)fkey(g_FS[gid]) << 32) | (u64)(0xFFFFFFFFu - i);
    u32 v0 = (u32)(g_prefix[b] & 0xFFFFu);
    u32 bin = (u32)(key >> 48);
    bool isDef = bin > v0, isCand = bin == v0;
    u32 md = __ballot_sync(0xFFFFFFFFu, isDef);
    if (isDef) {
        u32 pos = warp_append(&g_cnt[b], md);
        if (pos < K_TOP) g_sel[b][pos] = key;
    }
    u32 mc = __ballot_sync(0xFFFFFFFFu, isCand);
    if (isCand) {
        u32 pos = warp_append(&g_candn[b][0], mc);
        if (pos < CAND_MAX) g_cand[b][0][pos] = key;
        u32 bin2 = (u32)(key >> 32) & 0xFFFFu;
        hist_add(g_hist[1][b], g_coarse[1][b], bin2, mc);
    }
}

// level 1 over candidates: definite -> g_sel; exact-fkey ties -> cand[1]
__global__ void k_sel1() {
    int b = blockIdx.y;
    u32 N = g_candn[b][0];
    u32 v1 = (u32)(g_prefix[b] & 0xFFFFu);
    u32 total = (N + 255u) & ~255u;
    u32 t0 = blockIdx.x * blockDim.x + threadIdx.x;
    u32 stride = gridDim.x * blockDim.x;
    for (u32 t = t0; t < total; t += stride) {
        bool valid = t < N;
        u64 key = valid ? g_cand[b][0][t] : 0ull;
        u32 bin = (u32)(key >> 32) & 0xFFFFu;
        bool isDef = valid && (bin > v1);
        bool isTie = valid && (bin == v1);
        u32 md = __ballot_sync(0xFFFFFFFFu, isDef);
        if (isDef) {
            u32 pos = warp_append(&g_cnt[b], md);
            if (pos < K_TOP) g_sel[b][pos] = key;
        }
        u32 mt = __ballot_sync(0xFFFFFFFFu, isTie);
        if (isTie) {
            u32 pos = warp_append(&g_candn[b][1], mt);
            if (pos < CAND_MAX) g_cand[b][1][pos] = key;
        }
    }
}

// ties share exact fkey: take krem largest keys (= smallest indices) by rank
__global__ void k_tie() {
    int b = blockIdx.x;
    u32 N = g_candn[b][1];
    u32 need = g_krem[b];
    for (u32 t = threadIdx.x; t < N; t += 256) {
        u64 key = g_cand[b][1][t];
        u32 r = 0;
        for (u32 j = 0; j < N; j++) r += (g_cand[b][1][j] > key);
        if (r < need) {
            u32 pos = atomicAdd(&g_cnt[b], 1);
            if (pos < K_TOP) g_sel[b][pos] = key;
        }
    }
}

// rank-by-counting (keys unique): rank = #{keys greater}; emit kpts + topidx
__global__ void k_rank(float* __restrict__ dout) {
    int b = blockIdx.y;
    int i = blockIdx.x * 256 + threadIdx.x;
    u64 my = g_sel[b][i];
    __shared__ u64 tile[256];
    int r = 0;
    for (int t = 0; t < K_TOP; t += 256) {
        tile[threadIdx.x] = g_sel[b][t + threadIdx.x];
        __syncthreads();
        #pragma unroll 8
        for (int j = 0; j < 256; j++) r += (tile[j] > my);
        __syncthreads();
    }
    u32 idx = 0xFFFFFFFFu - (u32)my;
    g_topidx[b][r] = (int)idx;
    float x = (float)(idx % W_IMG), y = (float)(idx / W_IMG);
    dout[OFF_KPTS + (size_t)b * K_TOP * 2 + r * 2 + 0] = x;
    dout[OFF_KPTS + (size_t)b * K_TOP * 2 + r * 2 + 1] = y;
}

// grid-sample + renorm: 8 warps/block, one keypoint per warp (same per-warp math)
__global__ void k_desc() {
    int wrp = threadIdx.x >> 5, lane = threadIdx.x & 31;
    int k = blockIdx.x * 8 + wrp, b = blockIdx.y;
    int idx = g_topidx[b][k];
    float xf = (float)(idx % W_IMG), yf = (float)(idx / W_IMG);
    float gx = __fsub_rn(__fmul_rn(__fdiv_rn(xf, 639.f), 2.f), 1.f);
    float gy = __fsub_rn(__fmul_rn(__fdiv_rn(yf, 479.f), 2.f), 1.f);
    float ix = __fmul_rn(__fmul_rn(__fadd_rn(gx, 1.f), 0.5f), 79.f);
    float iy = __fmul_rn(__fmul_rn(__fadd_rn(gy, 1.f), 0.5f), 59.f);
    float ix0f = floorf(ix), iy0f = floorf(iy);
    float wx = __fsub_rn(ix, ix0f), wy = __fsub_rn(iy, iy0f);
    float omx = __fsub_rn(1.f, wx), omy = __fsub_rn(1.f, wy);
    int x0 = min(max((int)ix0f, 0), WC - 1), y0 = min(max((int)iy0f, 0), HC - 1);
    int x1 = min(x0 + 1, WC - 1), y1 = min(y0 + 1, HC - 1);
    int p00 = y0 * WC + x0, p01 = y0 * WC + x1, p10 = y1 * WC + x0, p11 = y1 * WC + x1;
    float v[2];
    #pragma unroll
    for (int t = 0; t < 2; t++) {
        int c = 2 * lane + t;
        const float* f = g_nf + ((size_t)b * CH + c) * NC;
        float t1 = __fmul_rn(__fmul_rn(f[p00], omx), omy);
        float t2 = __fmul_rn(__fmul_rn(f[p01], wx), omy);
        float t3 = __fmul_rn(__fmul_rn(f[p10], omx), wy);
        float t4 = __fmul_rn(__fmul_rn(f[p11], wx), wy);
        v[t] = __fadd_rn(__fadd_rn(__fadd_rn(t1, t2), t3), t4);
    }
    float pr = __fadd_rn(__fmul_rn(v[0], v[0]), __fmul_rn(v[1], v[1]));
    #pragma unroll
    for (int off = 16; off > 0; off >>= 1)
        pr = __fadd_rn(pr, __shfl_down_sync(0xFFFFFFFFu, pr, off));
    float n = fmaxf(__fsqrt_rn(__shfl_sync(0xFFFFFFFFu, pr, 0)), 1e-12f);
    g_desc[b][k][2 * lane + 0] = __fdiv_rn(v[0], n);
    g_desc[b][k][2 * lane + 1] = __fdiv_rn(v[1], n);
}

// sim: VALIDATED fp32 ascending-k FFMA chain; fused row/col argmax.
// Perf: cap regs at 128 (2 blocks/SM -> 4 warps/SMSP) to hide LDS latency.
#define TS 128
__global__ void __launch_bounds__(256, 2) k_sim() {
    extern __shared__ float sh[];
    float* As = sh;             // [64][128] k-major
    float* Bs = sh + 64 * TS;   // [64][128] k-major
    int tid = threadIdx.x;
    int rb = blockIdx.y * TS;
    int cb = blockIdx.x * TS;
    const float4* d0 = (const float4*)&g_desc[0][0][0];
    const float4* d1 = (const float4*)&g_desc[1][0][0];
    for (int t = tid; t < TS * 16; t += 256) {
        int r = t >> 4, c4 = t & 15;
        float4 a = d0[(size_t)(rb + r) * 16 + c4];
        As[(c4 * 4 + 0) * TS + r] = a.x; As[(c4 * 4 + 1) * TS + r] = a.y;
        As[(c4 * 4 + 2) * TS + r] = a.z; As[(c4 * 4 + 3) * TS + r] = a.w;
        float4 bv = d1[(size_t)(cb + r) * 16 + c4];
        Bs[(c4 * 4 + 0) * TS + r] = bv.x; Bs[(c4 * 4 + 1) * TS + r] = bv.y;
        Bs[(c4 * 4 + 2) * TS + r] = bv.z; Bs[(c4 * 4 + 3) * TS + r] = bv.w;
    }
    __syncthreads();
    int tx = tid & 15, ty = tid >> 4;
    float acc[8][8];
    #pragma unroll
    for (int i = 0; i < 8; i++)
        #pragma unroll
        for (int j = 0; j < 8; j++) acc[i][j] = 0.f;
    #pragma unroll 8
    for (int kk = 0; kk < 64; kk++) {     // strictly ascending k
        const float* Ak = As + kk * TS;
        const float* Bk = Bs + kk * TS;
        float4 a0 = *(const float4*)(Ak + ty * 4);
        float4 a1 = *(const float4*)(Ak + 64 + ty * 4);
        float4 b0 = *(const float4*)(Bk + tx * 4);
        float4 b1 = *(const float4*)(Bk + 64 + tx * 4);
        float av[8] = {a0.x, a0.y, a0.z, a0.w, a1.x, a1.y, a1.z, a1.w};
        float bv[8] = {b0.x, b0.y, b0.z, b0.w, b1.x, b1.y, b1.z, b1.w};
        #pragma unroll
        for (int i = 0; i < 8; i++)
            #pragma unroll
            for (int j = 0; j < 8; j++)
                acc[i][j] = __fmaf_rn(av[i], bv[j], acc[i][j]);
    }
    __syncthreads();
    u64* rowP = (u64*)sh;
    u64* colP = rowP + TS;
    if (tid < TS) { rowP[tid] = 0ull; colP[tid] = 0ull; }
    __syncthreads();
    #pragma unroll
    for (int i = 0; i < 8; i++) {
        int lr = (i < 4) ? (ty * 4 + i) : (64 + ty * 4 + i - 4);
        u64 best = 0ull;
        #pragma unroll
        for (int j = 0; j < 8; j++) {
            int gc = cb + ((j < 4) ? (tx * 4 + j) : (64 + tx * 4 + j - 4));
            u64 pk = ((u64)fkey(acc[i][j]) << 32) | (u64)(0xFFFFFFFFu - (u32)gc);
            if (pk > best) best = pk;
        }
        atomicMax(&rowP[lr], best);
    }
    #pragma unroll
    for (int j = 0; j < 8; j++) {
        int lc = (j < 4) ? (tx * 4 + j) : (64 + tx * 4 + j - 4);
        u64 best = 0ull;
        #pragma unroll
        for (int i = 0; i < 8; i++) {
            int gr = rb + ((i < 4) ? (ty * 4 + i) : (64 + ty * 4 + i - 4));
            u64 pk = ((u64)fkey(acc[i][j]) << 32) | (u64)(0xFFFFFFFFu - (u32)gr);
            if (pk > best) best = pk;
        }
        atomicMax(&colP[lc], best);
    }
    __syncthreads();
    if (tid < TS) {
        atomicMax(&g_rowP[rb + tid], rowP[tid]);
        atomicMax(&g_colP[cb + tid], colP[tid]);
    }
}

__global__ void k_final(float* __restrict__ dout) {
    int k = blockIdx.x * blockDim.x + threadIdx.x;   // exact: 4096
    u64 rp = g_rowP[k];
    float sc = unfkey((u32)(rp >> 32));
    u32 m01 = 0xFFFFFFFFu - (u32)rp;
    u64 cp = g_colP[m01];
    u32 m10 = 0xFFFFFFFFu - (u32)cp;
    bool valid = (m10 == (u32)k) && (sc > 0.1f);
    dout[OFF_MATCH + k] = (float)m01;
    dout[OFF_SCORE + k] = sc;
    dout[OFF_VALID + k] = valid ? 1.f : 0.f;
}

extern "C" void kernel_launch(void* const* d_in, const int* in_sizes, int n_in,
                              void* d_out, int out_size) {
    const float* feats   = (const float*)d_in[0];
    const float* logits  = (const float*)d_in[1];
    const float* heatmap = (const float*)d_in[2];
    float* out = (float*)d_out;

    cudaFuncSetAttribute(k_sim, cudaFuncAttributeMaxDynamicSharedMemorySize, 64 * TS * 2 * 4);

    k_init<<<256, 256>>>();
    k_prep<<<300, 256>>>(logits, feats);
    k_nms<<<2 * NPIX / 320, 320>>>(heatmap, out);
    k_scan<0><<<2, 256>>>();
    k_sel0<<<2 * NPIX / 256, 256>>>();
    k_scan<1><<<2, 256>>>();
    k_sel1<<<dim3(64, 2), 256>>>();
    k_tie<<<2, 256>>>();
    k_rank<<<dim3(K_TOP / 256, 2), 256>>>(out);
    k_desc<<<dim3(K_TOP / 8, 2), 256>>>();
    k_sim<<<dim3(K_TOP / TS, K_TOP / TS), 256, 64 * TS * 2 * 4>>>();
    k_final<<<K_TOP / 256, 256>>>(out);
}

// round 15
// speedup vs baseline: 1.0730x; 1.0730x over previous
#include <cuda_runtime.h>

typedef unsigned int u32;
typedef unsigned long long u64;

extern "C" __device__ float __nv_expf(float);   // libdevice expf (matches XLA)

#define K_TOP 4096
#define W_IMG 640
#define H_IMG 480
#define NPIX (W_IMG * H_IMG)      // 307200
#define WC 80
#define HC 60
#define NC (WC * HC)              // 4800
#define CH 64
#define CAND_MAX 320000

#define OFF_KPTS  0
#define OFF_MATCH 16384
#define OFF_SCORE 20480
#define OFF_VALID 24576
#define OFF_H     28672
#define OFF_R     643072

__device__ float g_Hs[2 * NPIX];
__device__ float g_FS[2 * NPIX];
__device__ float g_nf[2 * CH * NC];
__device__ u32   g_hist[2][2][65536];
__device__ u32   g_coarse[2][2][256];
__device__ u64   g_prefix[2];
__device__ u32   g_krem[2];
__device__ u32   g_cnt[2];
__device__ u32   g_candn[2][2];
__device__ u64   g_cand[2][2][CAND_MAX];
__device__ u64   g_sel[2][K_TOP];
__device__ int   g_topidx[2][K_TOP];
__device__ float g_desc[2][K_TOP][CH];
__device__ u64   g_rowP[K_TOP];
__device__ u64   g_colP[K_TOP];

__device__ __forceinline__ u32 fkey(float f) {
    u32 u = __float_as_uint(f);
    return (u >> 31) ? ~u : (u | 0x80000000u);
}
__device__ __forceinline__ float unfkey(u32 k) {
    return __uint_as_float((k >> 31) ? (k & 0x7FFFFFFFu) : ~k);
}

#define PACKF2(out, lo, hi) asm("mov.b64 %0, {%1, %2};" : "=l"(out) : "f"(lo), "f"(hi))
#define UNPACKF2(lo, hi, in) asm("mov.b64 {%0, %1}, %2;" : "=f"(lo), "=f"(hi) : "l"(in))
#define FMA2(acc, a, b) asm("fma.rn.f32x2 %0, %1, %2, %0;" : "+l"(acc) : "l"(a), "l"(b))

__device__ __forceinline__ u32 warp_append(u32* counter, u32 mask) {
    int lane = threadIdx.x & 31;
    u32 ldr = __ffs(mask) - 1;
    u32 base = 0;
    if ((u32)lane == ldr) base = atomicAdd(counter, __popc(mask));
    base = __shfl_sync(mask, base, ldr);
    return base + __popc(mask & ((1u << lane) - 1));
}

// aggregated histogram add for fine+coarse (mask = active lanes)
__device__ __forceinline__ void hist_add(u32* fine, u32* coarse, u32 bin, u32 mask) {
    u32 peers = __match_any_sync(mask, bin);
    if ((u32)(__ffs(peers) - 1) == (threadIdx.x & 31u))
        atomicAdd(&fine[bin], __popc(peers));
    u32 cbin = bin >> 8;
    u32 cpeers = __match_any_sync(mask, cbin);
    if ((u32)(__ffs(cpeers) - 1) == (threadIdx.x & 31u))
        atomicAdd(&coarse[cbin], __popc(cpeers));
}

__global__ void k_init() {
    int i = blockIdx.x * blockDim.x + threadIdx.x;
    int st = blockDim.x * gridDim.x;
    u32* h = &g_hist[0][0][0];
    for (int j = i; j < 2 * 2 * 65536; j += st) h[j] = 0;
    u32* c = &g_coarse[0][0][0];
    for (int j = i; j < 2 * 2 * 256; j += st) c[j] = 0;
    for (int j = i; j < K_TOP; j += st) { g_rowP[j] = 0ull; g_colP[j] = 0ull; }
    if (i < 2) {
        g_prefix[i] = 0ull; g_krem[i] = K_TOP; g_cnt[i] = 0;
        g_candn[i][0] = 0; g_candn[i][1] = 0;
    }
}

// fused: blocks 0..149 softmax+shuffle (XLA column-reduce order),
//        blocks 150..299 feats norm (same association). smem-staged coalesced.
__global__ void k_prep(const float* __restrict__ logits,
                       const float* __restrict__ feats) {
    __shared__ float sm[65 * 65 + 65];
    int blk = blockIdx.x;
    int lane = threadIdx.x & 31, wrp = threadIdx.x >> 5;
    if (blk < 150) {
        int b = blk / 75;
        int cellbase = (blk % 75) * 64;
        const float* p = logits + (size_t)b * 65 * NC + cellbase;
        for (int i = threadIdx.x; i < 65 * 64; i += 256) {
            int ch = i >> 6, cl = i & 63;
            sm[ch * 65 + cl] = p[ch * NC + cl];
        }
        __syncthreads();
        float* out = g_Hs + (size_t)b * NPIX;
        #pragma unroll
        for (int s = 0; s < 8; s++) {
            int cell = wrp * 8 + s;
            float x0 = sm[lane * 65 + cell];
            float x1 = sm[(lane + 32) * 65 + cell];
            float x2 = (lane == 0) ? sm[64 * 65 + cell] : __int_as_float(0xff800000);
            float m = fmaxf(fmaxf(x0, x1), x2);
            #pragma unroll
            for (int off = 16; off > 0; off >>= 1)
                m = fmaxf(m, __shfl_xor_sync(0xFFFFFFFFu, m, off));
            float e0 = __nv_expf(__fsub_rn(x0, m));
            float e1 = __nv_expf(__fsub_rn(x1, m));
            float e2 = __nv_expf(__fsub_rn(x2, m));
            float partial = __fadd_rn(__fadd_rn(e0, e1), e2);
            #pragma unroll
            for (int off = 16; off > 0; off >>= 1)
                partial = __fadd_rn(partial, __shfl_down_sync(0xFFFFFFFFu, partial, off));
            float ssum = __shfl_sync(0xFFFFFFFFu, partial, 0);
            int gcell = cellbase + cell;
            int h = gcell / WC, w = gcell % WC;
            int c0 = lane, c1 = lane + 32;
            out[(h * 8 + (c0 >> 3)) * W_IMG + (w * 8 + (c0 & 7))] = __fdiv_rn(e0, ssum);
            out[(h * 8 + (c1 >> 3)) * W_IMG + (w * 8 + (c1 & 7))] = __fdiv_rn(e1, ssum);
        }
    } else {
        int blk2 = blk - 150;
        int b = blk2 / 75;
        int cellbase = (blk2 % 75) * 64;
        float* nrm = sm + 64 * 65;
        const float* f = feats + (size_t)b * CH * NC + cellbase;
        float* o = g_nf + (size_t)b * CH * NC + cellbase;
        for (int i = threadIdx.x; i < 64 * 64; i += 256) {
            int ch = i >> 6, cl = i & 63;
            sm[ch * 65 + cl] = f[ch * NC + cl];
        }
        __syncthreads();
        #pragma unroll
        for (int s = 0; s < 8; s++) {
            int cell = wrp * 8 + s;
            float x0 = sm[lane * 65 + cell];
            float x1 = sm[(lane + 32) * 65 + cell];
            float partial = __fadd_rn(__fmul_rn(x0, x0), __fmul_rn(x1, x1));
            #pragma unroll
            for (int off = 16; off > 0; off >>= 1)
                partial = __fadd_rn(partial, __shfl_down_sync(0xFFFFFFFFu, partial, off));
            if (lane == 0) nrm[cell] = fmaxf(__fsqrt_rn(partial), 1e-12f);
        }
        __syncthreads();
        for (int i = threadIdx.x; i < 64 * 64; i += 256) {
            int ch = i >> 6, cl = i & 63;
            o[ch * NC + cl] = __fdiv_rn(sm[ch * 65 + cl], nrm[cl]);
        }
    }
}

// 5x5 NMS (smem-tiled) + bilinear reliability + level-0 fine+coarse hist
__global__ void k_nms(const float* __restrict__ heatmap, float* __restrict__ dout) {
    __shared__ float tile[5][324];
    int tid = threadIdx.x;                       // 320 threads
    int gid = blockIdx.x * 320 + tid;            // exact: 2*NPIX (1920 blocks)
    int b = gid / NPIX, p = gid % NPIX;
    int oy = p / W_IMG;
    int xbase = p % W_IMG - tid;                 // 0 or 320 (strip base)
    const float* Hs = g_Hs + (size_t)b * NPIX;
    for (int i = tid; i < 5 * 324; i += 320) {
        int rr = i / 324, cc = i % 324;
        int row = oy - 2 + rr, col = xbase - 2 + cc;
        float v = __int_as_float(0xff800000);
        if ((unsigned)row < H_IMG && (unsigned)col < W_IMG)
            v = Hs[row * W_IMG + col];
        tile[rr][cc] = v;
    }
    __syncthreads();
    int ox = xbase + tid;

    float sy = __fsub_rn(__fmul_rn(__fadd_rn((float)oy, 0.5f), 0.125f), 0.5f);
    float sx = __fsub_rn(__fmul_rn(__fadd_rn((float)ox, 0.5f), 0.125f), 0.5f);
    int iy0 = (int)floorf(sy);
    int ix0 = (int)floorf(sx);
    float fy = __fsub_rn(sy, (float)iy0);
    float fx = __fsub_rn(sx, (float)ix0);
    int y0 = iy0 < 0 ? 0 : iy0;
    int y1 = iy0 >= HC - 1 ? HC - 1 : iy0 + 1;
    int x0 = ix0 < 0 ? 0 : ix0;
    int x1 = ix0 >= WC - 1 ? WC - 1 : ix0 + 1;
    float wy0 = iy0 < 0 ? 0.f : (iy0 >= HC - 1 ? 1.f : __fsub_rn(1.f, fy));
    float wy1 = iy0 < 0 ? 1.f : (iy0 >= HC - 1 ? 0.f : fy);
    float wx0 = ix0 < 0 ? 0.f : (ix0 >= WC - 1 ? 1.f : __fsub_rn(1.f, fx));
    float wx1 = ix0 < 0 ? 1.f : (ix0 >= WC - 1 ? 0.f : fx);
    const float* hm = heatmap + (size_t)b * NC;
    float t0 = __fmaf_rn(wx1, hm[y0 * WC + x1], __fmul_rn(wx0, hm[y0 * WC + x0]));
    float t1 = __fmaf_rn(wx1, hm[y1 * WC + x1], __fmul_rn(wx0, hm[y1 * WC + x0]));
    float rel = __fmaf_rn(wy1, t1, __fmul_rn(wy0, t0));

    float x = tile[2][tid + 2];
    float lm = x;
    #pragma unroll
    for (int dy = 0; dy < 5; dy++)
        #pragma unroll
        for (int dx = 0; dx < 5; dx++)
            lm = fmaxf(lm, tile[dy][tid + dx]);
    float fs = (x == lm) ? __fmul_rn(x, rel) : 0.f;
    if (fs == 0.f) fs = 0.f;   // canonicalize -0
    g_FS[gid] = fs;
    dout[OFF_H + gid] = fs;
    dout[OFF_R + gid] = rel;

    u32 bin = fkey(fs) >> 16;
    hist_add(g_hist[0][b], g_coarse[0][b], bin, 0xFFFFFFFFu);
}

// threshold scan: parallel suffix-sum pick (identical integer results)
template <int L>
__global__ void k_scan() {
    int b = blockIdx.x;
    __shared__ u32 bufA[256], bufB[256];
    __shared__ int csel;
    __shared__ u32 krem2s;
    int t = threadIdx.x;
    u32 krem = g_krem[b];

    bufA[t] = g_coarse[L][b][t];
    __syncthreads();
    u32* cur = bufA; u32* nxt = bufB;
    #pragma unroll
    for (int off = 1; off < 256; off <<= 1) {
        u32 v = cur[t] + ((t + off < 256) ? cur[t + off] : 0u);
        __syncthreads();
        nxt[t] = v;
        __syncthreads();
        u32* tmp = cur; cur = nxt; nxt = tmp;
    }
    u32 sufN = (t == 255) ? 0u : cur[t + 1];
    if (cur[t] >= krem && sufN < krem) { csel = t; krem2s = krem - sufN; }
    __syncthreads();
    int cs = csel;
    u32 krem2 = krem2s;
    __syncthreads();

    bufA[t] = g_hist[L][b][cs * 256 + t];
    __syncthreads();
    cur = bufA; nxt = bufB;
    #pragma unroll
    for (int off = 1; off < 256; off <<= 1) {
        u32 v = cur[t] + ((t + off < 256) ? cur[t + off] : 0u);
        __syncthreads();
        nxt[t] = v;
        __syncthreads();
        u32* tmp = cur; cur = nxt; nxt = tmp;
    }
    u32 sufNf = (t == 255) ? 0u : cur[t + 1];
    if (cur[t] >= krem2 && sufNf < krem2) {
        g_krem[b] = krem2 - sufNf;
        g_prefix[b] = (g_prefix[b] << 16) | (u64)(u32)(cs * 256 + t);
    }
}

// full pass: definite -> g_sel; threshold-bin -> cand[0] + level-1 fine+coarse
__global__ void k_sel0() {
    int gid = blockIdx.x * blockDim.x + threadIdx.x;   // exact: 2*NPIX
    int b = gid / NPIX;
    u32 i = gid % NPIX;
    u64 key = ((u64)fkey(g_FS[gid]) << 32) | (u64)(0xFFFFFFFFu - i);
    u32 v0 = (u32)(g_prefix[b] & 0xFFFFu);
    u32 bin = (u32)(key >> 48);
    bool isDef = bin > v0, isCand = bin == v0;
    u32 md = __ballot_sync(0xFFFFFFFFu, isDef);
    if (isDef) {
        u32 pos = warp_append(&g_cnt[b], md);
        if (pos < K_TOP) g_sel[b][pos] = key;
    }
    u32 mc = __ballot_sync(0xFFFFFFFFu, isCand);
    if (isCand) {
        u32 pos = warp_append(&g_candn[b][0], mc);
        if (pos < CAND_MAX) g_cand[b][0][pos] = key;
        u32 bin2 = (u32)(key >> 32) & 0xFFFFu;
        hist_add(g_hist[1][b], g_coarse[1][b], bin2, mc);
    }
}

// level 1 over candidates: definite -> g_sel; exact-fkey ties -> cand[1]
__global__ void k_sel1() {
    int b = blockIdx.y;
    u32 N = g_candn[b][0];
    u32 v1 = (u32)(g_prefix[b] & 0xFFFFu);
    u32 total = (N + 255u) & ~255u;
    u32 t0 = blockIdx.x * blockDim.x + threadIdx.x;
    u32 stride = gridDim.x * blockDim.x;
    for (u32 t = t0; t < total; t += stride) {
        bool valid = t < N;
        u64 key = valid ? g_cand[b][0][t] : 0ull;
        u32 bin = (u32)(key >> 32) & 0xFFFFu;
        bool isDef = valid && (bin > v1);
        bool isTie = valid && (bin == v1);
        u32 md = __ballot_sync(0xFFFFFFFFu, isDef);
        if (isDef) {
            u32 pos = warp_append(&g_cnt[b], md);
            if (pos < K_TOP) g_sel[b][pos] = key;
        }
        u32 mt = __ballot_sync(0xFFFFFFFFu, isTie);
        if (isTie) {
            u32 pos = warp_append(&g_candn[b][1], mt);
            if (pos < CAND_MAX) g_cand[b][1][pos] = key;
        }
    }
}

// ties share exact fkey: take krem largest keys (= smallest indices) by rank
__global__ void k_tie() {
    int b = blockIdx.x;
    u32 N = g_candn[b][1];
    u32 need = g_krem[b];
    for (u32 t = threadIdx.x; t < N; t += 256) {
        u64 key = g_cand[b][1][t];
        u32 r = 0;
        for (u32 j = 0; j < N; j++) r += (g_cand[b][1][j] > key);
        if (r < need) {
            u32 pos = atomicAdd(&g_cnt[b], 1);
            if (pos < K_TOP) g_sel[b][pos] = key;
        }
    }
}

// rank-by-counting (keys unique): rank = #{keys greater}; emit kpts + topidx
__global__ void k_rank(float* __restrict__ dout) {
    int b = blockIdx.y;
    int i = blockIdx.x * 256 + threadIdx.x;
    u64 my = g_sel[b][i];
    __shared__ u64 tile[256];
    int r = 0;
    for (int t = 0; t < K_TOP; t += 256) {
        tile[threadIdx.x] = g_sel[b][t + threadIdx.x];
        __syncthreads();
        #pragma unroll 8
        for (int j = 0; j < 256; j++) r += (tile[j] > my);
        __syncthreads();
    }
    u32 idx = 0xFFFFFFFFu - (u32)my;
    g_topidx[b][r] = (int)idx;
    float x = (float)(idx % W_IMG), y = (float)(idx / W_IMG);
    dout[OFF_KPTS + (size_t)b * K_TOP * 2 + r * 2 + 0] = x;
    dout[OFF_KPTS + (size_t)b * K_TOP * 2 + r * 2 + 1] = y;
}

// grid-sample + renorm: 8 warps/block, one keypoint per warp (same per-warp math)
__global__ void k_desc() {
    int wrp = threadIdx.x >> 5, lane = threadIdx.x & 31;
    int k = blockIdx.x * 8 + wrp, b = blockIdx.y;
    int idx = g_topidx[b][k];
    float xf = (float)(idx % W_IMG), yf = (float)(idx / W_IMG);
    float gx = __fsub_rn(__fmul_rn(__fdiv_rn(xf, 639.f), 2.f), 1.f);
    float gy = __fsub_rn(__fmul_rn(__fdiv_rn(yf, 479.f), 2.f), 1.f);
    float ix = __fmul_rn(__fmul_rn(__fadd_rn(gx, 1.f), 0.5f), 79.f);
    float iy = __fmul_rn(__fmul_rn(__fadd_rn(gy, 1.f), 0.5f), 59.f);
    float ix0f = floorf(ix), iy0f = floorf(iy);
    float wx = __fsub_rn(ix, ix0f), wy = __fsub_rn(iy, iy0f);
    float omx = __fsub_rn(1.f, wx), omy = __fsub_rn(1.f, wy);
    int x0 = min(max((int)ix0f, 0), WC - 1), y0 = min(max((int)iy0f, 0), HC - 1);
    int x1 = min(x0 + 1, WC - 1), y1 = min(y0 + 1, HC - 1);
    int p00 = y0 * WC + x0, p01 = y0 * WC + x1, p10 = y1 * WC + x0, p11 = y1 * WC + x1;
    float v[2];
    #pragma unroll
    for (int t = 0; t < 2; t++) {
        int c = 2 * lane + t;
        const float* f = g_nf + ((size_t)b * CH + c) * NC;
        float t1 = __fmul_rn(__fmul_rn(f[p00], omx), omy);
        float t2 = __fmul_rn(__fmul_rn(f[p01], wx), omy);
        float t3 = __fmul_rn(__fmul_rn(f[p10], omx), wy);
        float t4 = __fmul_rn(__fmul_rn(f[p11], wx), wy);
        v[t] = __fadd_rn(__fadd_rn(__fadd_rn(t1, t2), t3), t4);
    }
    float pr = __fadd_rn(__fmul_rn(v[0], v[0]), __fmul_rn(v[1], v[1]));
    #pragma unroll
    for (int off = 16; off > 0; off >>= 1)
        pr = __fadd_rn(pr, __shfl_down_sync(0xFFFFFFFFu, pr, off));
    float n = fmaxf(__fsqrt_rn(__shfl_sync(0xFFFFFFFFu, pr, 0)), 1e-12f);
    g_desc[b][k][2 * lane + 0] = __fdiv_rn(v[0], n);
    g_desc[b][k][2 * lane + 1] = __fdiv_rn(v[1], n);
}

// sim: VALIDATED fp32 ascending-k chain per output; packed fma.rn.f32x2
// (two adjacent-column outputs per instruction; per-lane math bit-identical).
#define TS 128
__global__ void k_sim() {
    extern __shared__ float sh[];
    float* As = sh;             // [64][128] k-major
    float* Bs = sh + 64 * TS;   // [64][128] k-major
    int tid = threadIdx.x;
    int rb = blockIdx.y * TS;
    int cb = blockIdx.x * TS;
    const float4* d0 = (const float4*)&g_desc[0][0][0];
    const float4* d1 = (const float4*)&g_desc[1][0][0];
    for (int t = tid; t < TS * 16; t += 256) {
        int r = t >> 4, c4 = t & 15;
        float4 a = d0[(size_t)(rb + r) * 16 + c4];
        As[(c4 * 4 + 0) * TS + r] = a.x; As[(c4 * 4 + 1) * TS + r] = a.y;
        As[(c4 * 4 + 2) * TS + r] = a.z; As[(c4 * 4 + 3) * TS + r] = a.w;
        float4 bv = d1[(size_t)(cb + r) * 16 + c4];
        Bs[(c4 * 4 + 0) * TS + r] = bv.x; Bs[(c4 * 4 + 1) * TS + r] = bv.y;
        Bs[(c4 * 4 + 2) * TS + r] = bv.z; Bs[(c4 * 4 + 3) * TS + r] = bv.w;
    }
    __syncthreads();
    int tx = tid & 15, ty = tid >> 4;
    u64 acc2[8][4];                     // [row i][col-pair j2]: cols 2j2, 2j2+1
    #pragma unroll
    for (int i = 0; i < 8; i++)
        #pragma unroll
        for (int j2 = 0; j2 < 4; j2++) acc2[i][j2] = 0ull;
    #pragma unroll 4
    for (int kk = 0; kk < 64; kk++) {   // strictly ascending k
        const float* Ak = As + kk * TS;
        const float* Bk = Bs + kk * TS;
        float4 a0 = *(const float4*)(Ak + ty * 4);
        float4 a1 = *(const float4*)(Ak + 64 + ty * 4);
        float av[8] = {a0.x, a0.y, a0.z, a0.w, a1.x, a1.y, a1.z, a1.w};
        u64 ap[8];
        #pragma unroll
        for (int i = 0; i < 8; i++) PACKF2(ap[i], av[i], av[i]);
        u64 bp[4];
        bp[0] = *(const u64*)(Bk + tx * 4);
        bp[1] = *(const u64*)(Bk + tx * 4 + 2);
        bp[2] = *(const u64*)(Bk + 64 + tx * 4);
        bp[3] = *(const u64*)(Bk + 64 + tx * 4 + 2);
        #pragma unroll
        for (int i = 0; i < 8; i++)
            #pragma unroll
            for (int j2 = 0; j2 < 4; j2++)
                FMA2(acc2[i][j2], ap[i], bp[j2]);
    }
    __syncthreads();
    u64* rowP = (u64*)sh;
    u64* colP = rowP + TS;
    if (tid < TS) { rowP[tid] = 0ull; colP[tid] = 0ull; }
    __syncthreads();
    #pragma unroll
    for (int i = 0; i < 8; i++) {
        int lr = (i < 4) ? (ty * 4 + i) : (64 + ty * 4 + i - 4);
        u64 best = 0ull;
        #pragma unroll
        for (int j2 = 0; j2 < 4; j2++) {
            float lo, hi;
            UNPACKF2(lo, hi, acc2[i][j2]);
            int j = 2 * j2;
            int gc = cb + ((j < 4) ? (tx * 4 + j) : (64 + tx * 4 + j - 4));
            u64 k0 = ((u64)fkey(lo) << 32) | (u64)(0xFFFFFFFFu - (u32)gc);
            u64 k1 = ((u64)fkey(hi) << 32) | (u64)(0xFFFFFFFFu - (u32)(gc + 1));
            best = max(best, max(k0, k1));
        }
        atomicMax(&rowP[lr], best);
    }
    #pragma unroll
    for (int j2 = 0; j2 < 4; j2++) {
        int j = 2 * j2;
        int lc = (j < 4) ? (tx * 4 + j) : (64 + tx * 4 + j - 4);
        u64 b0 = 0ull, b1 = 0ull;
        #pragma unroll
        for (int i = 0; i < 8; i++) {
            float lo, hi;
            UNPACKF2(lo, hi, acc2[i][j2]);
            u32 gr = (u32)(rb + ((i < 4) ? (ty * 4 + i) : (64 + ty * 4 + i - 4)));
            b0 = max(b0, ((u64)fkey(lo) << 32) | (u64)(0xFFFFFFFFu - gr));
            b1 = max(b1, ((u64)fkey(hi) << 32) | (u64)(0xFFFFFFFFu - gr));
        }
        atomicMax(&colP[lc], b0);
        atomicMax(&colP[lc + 1], b1);
    }
    __syncthreads();
    if (tid < TS) {
        atomicMax(&g_rowP[rb + tid], rowP[tid]);
        atomicMax(&g_colP[cb + tid], colP[tid]);
    }
}

__global__ void k_final(float* __restrict__ dout) {
    int k = blockIdx.x * blockDim.x + threadIdx.x;   // exact: 4096
    u64 rp = g_rowP[k];
    float sc = unfkey((u32)(rp >> 32));
    u32 m01 = 0xFFFFFFFFu - (u32)rp;
    u64 cp = g_colP[m01];
    u32 m10 = 0xFFFFFFFFu - (u32)cp;
    bool valid = (m10 == (u32)k) && (sc > 0.1f);
    dout[OFF_MATCH + k] = (float)m01;
    dout[OFF_SCORE + k] = sc;
    dout[OFF_VALID + k] = valid ? 1.f : 0.f;
}

extern "C" void kernel_launch(void* const* d_in, const int* in_sizes, int n_in,
                              void* d_out, int out_size) {
    const float* feats   = (const float*)d_in[0];
    const float* logits  = (const float*)d_in[1];
    const float* heatmap = (const float*)d_in[2];
    float* out = (float*)d_out;

    cudaFuncSetAttribute(k_sim, cudaFuncAttributeMaxDynamicSharedMemorySize, 64 * TS * 2 * 4);

    k_init<<<256, 256>>>();
    k_prep<<<300, 256>>>(logits, feats);
    k_nms<<<2 * NPIX / 320, 320>>>(heatmap, out);
    k_scan<0><<<2, 256>>>();
    k_sel0<<<2 * NPIX / 256, 256>>>();
    k_scan<1><<<2, 256>>>();
    k_sel1<<<dim3(64, 2), 256>>>();
    k_tie<<<2, 256>>>();
    k_rank<<<dim3(K_TOP / 256, 2), 256>>>(out);
    k_desc<<<dim3(K_TOP / 8, 2), 256>>>();
    k_sim<<<dim3(K_TOP / TS, K_TOP / TS), 256, 64 * TS * 2 * 4>>>();
    k_final<<<K_TOP / 256, 256>>>(out);
}

// round 16
// speedup vs baseline: 1.1076x; 1.0323x over previous
#include <cuda_runtime.h>

typedef unsigned int u32;
typedef unsigned long long u64;

extern "C" __device__ float __nv_expf(float);   // libdevice expf (matches XLA)

#define K_TOP 4096
#define W_IMG 640
#define H_IMG 480
#define NPIX (W_IMG * H_IMG)      // 307200
#define WC 80
#define HC 60
#define NC (WC * HC)              // 4800
#define CH 64
#define CAND_MAX 320000

#define OFF_KPTS  0
#define OFF_MATCH 16384
#define OFF_SCORE 20480
#define OFF_VALID 24576
#define OFF_H     28672
#define OFF_R     643072

__device__ float g_Hs[2 * NPIX];
__device__ float g_FS[2 * NPIX];
__device__ float g_nf[2 * CH * NC];
__device__ u32   g_hist[2][2][65536];
__device__ u32   g_coarse[2][2][256];
__device__ u64   g_prefix[2];
__device__ u32   g_krem[2];
__device__ u32   g_cnt[2];
__device__ u32   g_candn[2][2];
__device__ u64   g_cand[2][2][CAND_MAX];
__device__ u64   g_sel[2][K_TOP];
__device__ int   g_topidx[2][K_TOP];
__device__ float g_desc[2][K_TOP][CH];
__device__ u64   g_rowP[K_TOP];
__device__ u64   g_colP[K_TOP];

__device__ __forceinline__ u32 fkey(float f) {
    u32 u = __float_as_uint(f);
    return (u >> 31) ? ~u : (u | 0x80000000u);
}
__device__ __forceinline__ float unfkey(u32 k) {
    return __uint_as_float((k >> 31) ? (k & 0x7FFFFFFFu) : ~k);
}

#define PACKF2(out, lo, hi) asm("mov.b64 %0, {%1, %2};" : "=l"(out) : "f"(lo), "f"(hi))
#define UNPACKF2(lo, hi, in) asm("mov.b64 {%0, %1}, %2;" : "=f"(lo), "=f"(hi) : "l"(in))
#define FMA2(acc, a, b) asm("fma.rn.f32x2 %0, %1, %2, %0;" : "+l"(acc) : "l"(a), "l"(b))

__device__ __forceinline__ u32 warp_append(u32* counter, u32 mask) {
    int lane = threadIdx.x & 31;
    u32 ldr = __ffs(mask) - 1;
    u32 base = 0;
    if ((u32)lane == ldr) base = atomicAdd(counter, __popc(mask));
    base = __shfl_sync(mask, base, ldr);
    return base + __popc(mask & ((1u << lane) - 1));
}

// aggregated histogram add for fine+coarse (mask = active lanes)
__device__ __forceinline__ void hist_add(u32* fine, u32* coarse, u32 bin, u32 mask) {
    u32 peers = __match_any_sync(mask, bin);
    if ((u32)(__ffs(peers) - 1) == (threadIdx.x & 31u))
        atomicAdd(&fine[bin], __popc(peers));
    u32 cbin = bin >> 8;
    u32 cpeers = __match_any_sync(mask, cbin);
    if ((u32)(__ffs(cpeers) - 1) == (threadIdx.x & 31u))
        atomicAdd(&coarse[cbin], __popc(cpeers));
}

// fused: blocks 0..149 softmax+shuffle, 150..299 feats norm, 300..555 scratch init
__global__ void k_prep(const float* __restrict__ logits,
                       const float* __restrict__ feats) {
    __shared__ float sm[65 * 65 + 65];
    int blk = blockIdx.x;
    int lane = threadIdx.x & 31, wrp = threadIdx.x >> 5;
    if (blk >= 300) {
        int i = (blk - 300) * 256 + threadIdx.x;
        int st = 256 * 256;
        u32* h = &g_hist[0][0][0];
        for (int j = i; j < 2 * 2 * 65536; j += st) h[j] = 0;
        u32* c = &g_coarse[0][0][0];
        for (int j = i; j < 2 * 2 * 256; j += st) c[j] = 0;
        for (int j = i; j < K_TOP; j += st) { g_rowP[j] = 0ull; g_colP[j] = 0ull; }
        if (i < 2) {
            g_prefix[i] = 0ull; g_krem[i] = K_TOP; g_cnt[i] = 0;
            g_candn[i][0] = 0; g_candn[i][1] = 0;
        }
        return;
    }
    if (blk < 150) {
        int b = blk / 75;
        int cellbase = (blk % 75) * 64;
        const float* p = logits + (size_t)b * 65 * NC + cellbase;
        for (int i = threadIdx.x; i < 65 * 64; i += 256) {
            int ch = i >> 6, cl = i & 63;
            sm[ch * 65 + cl] = p[ch * NC + cl];
        }
        __syncthreads();
        float* out = g_Hs + (size_t)b * NPIX;
        #pragma unroll
        for (int s = 0; s < 8; s++) {
            int cell = wrp * 8 + s;
            float x0 = sm[lane * 65 + cell];
            float x1 = sm[(lane + 32) * 65 + cell];
            float x2 = (lane == 0) ? sm[64 * 65 + cell] : __int_as_float(0xff800000);
            float m = fmaxf(fmaxf(x0, x1), x2);
            #pragma unroll
            for (int off = 16; off > 0; off >>= 1)
                m = fmaxf(m, __shfl_xor_sync(0xFFFFFFFFu, m, off));
            float e0 = __nv_expf(__fsub_rn(x0, m));
            float e1 = __nv_expf(__fsub_rn(x1, m));
            float e2 = __nv_expf(__fsub_rn(x2, m));
            float partial = __fadd_rn(__fadd_rn(e0, e1), e2);
            #pragma unroll
            for (int off = 16; off > 0; off >>= 1)
                partial = __fadd_rn(partial, __shfl_down_sync(0xFFFFFFFFu, partial, off));
            float ssum = __shfl_sync(0xFFFFFFFFu, partial, 0);
            int gcell = cellbase + cell;
            int h = gcell / WC, w = gcell % WC;
            int c0 = lane, c1 = lane + 32;
            out[(h * 8 + (c0 >> 3)) * W_IMG + (w * 8 + (c0 & 7))] = __fdiv_rn(e0, ssum);
            out[(h * 8 + (c1 >> 3)) * W_IMG + (w * 8 + (c1 & 7))] = __fdiv_rn(e1, ssum);
        }
    } else {
        int blk2 = blk - 150;
        int b = blk2 / 75;
        int cellbase = (blk2 % 75) * 64;
        float* nrm = sm + 64 * 65;
        const float* f = feats + (size_t)b * CH * NC + cellbase;
        float* o = g_nf + (size_t)b * CH * NC + cellbase;
        for (int i = threadIdx.x; i < 64 * 64; i += 256) {
            int ch = i >> 6, cl = i & 63;
            sm[ch * 65 + cl] = f[ch * NC + cl];
        }
        __syncthreads();
        #pragma unroll
        for (int s = 0; s < 8; s++) {
            int cell = wrp * 8 + s;
            float x0 = sm[lane * 65 + cell];
            float x1 = sm[(lane + 32) * 65 + cell];
            float partial = __fadd_rn(__fmul_rn(x0, x0), __fmul_rn(x1, x1));
            #pragma unroll
            for (int off = 16; off > 0; off >>= 1)
                partial = __fadd_rn(partial, __shfl_down_sync(0xFFFFFFFFu, partial, off));
            if (lane == 0) nrm[cell] = fmaxf(__fsqrt_rn(partial), 1e-12f);
        }
        __syncthreads();
        for (int i = threadIdx.x; i < 64 * 64; i += 256) {
            int ch = i >> 6, cl = i & 63;
            o[ch * NC + cl] = __fdiv_rn(sm[ch * 65 + cl], nrm[cl]);
        }
    }
}

// 5x5 NMS, 2D tiles 128x16 outputs (halo 132x20) + bilinear + level-0 hist
__global__ void k_nms(const float* __restrict__ heatmap, float* __restrict__ dout) {
    __shared__ float tile[20][132];
    int b = blockIdx.z;
    int xbase = blockIdx.x * 128;
    int ybase = blockIdx.y * 16;
    int tid = threadIdx.x;                 // 256 threads
    const float* Hs = g_Hs + (size_t)b * NPIX;
    for (int i = tid; i < 20 * 132; i += 256) {
        int rr = i / 132, cc = i % 132;
        int row = ybase - 2 + rr, col = xbase - 2 + cc;
        float v = __int_as_float(0xff800000);
        if ((unsigned)row < H_IMG && (unsigned)col < W_IMG)
            v = Hs[row * W_IMG + col];
        tile[rr][cc] = v;
    }
    __syncthreads();
    int c = tid & 127, r0 = tid >> 7;      // 128 cols x 2 rows, 8 passes
    const float* hm = heatmap + (size_t)b * NC;
    #pragma unroll
    for (int pass = 0; pass < 8; pass++) {
        int lr = r0 + 2 * pass;            // local row 0..15
        int oy = ybase + lr, ox = xbase + c;

        float sy = __fsub_rn(__fmul_rn(__fadd_rn((float)oy, 0.5f), 0.125f), 0.5f);
        float sx = __fsub_rn(__fmul_rn(__fadd_rn((float)ox, 0.5f), 0.125f), 0.5f);
        int iy0 = (int)floorf(sy);
        int ix0 = (int)floorf(sx);
        float fy = __fsub_rn(sy, (float)iy0);
        float fx = __fsub_rn(sx, (float)ix0);
        int y0 = iy0 < 0 ? 0 : iy0;
        int y1 = iy0 >= HC - 1 ? HC - 1 : iy0 + 1;
        int x0 = ix0 < 0 ? 0 : ix0;
        int x1 = ix0 >= WC - 1 ? WC - 1 : ix0 + 1;
        float wy0 = iy0 < 0 ? 0.f : (iy0 >= HC - 1 ? 1.f : __fsub_rn(1.f, fy));
        float wy1 = iy0 < 0 ? 1.f : (iy0 >= HC - 1 ? 0.f : fy);
        float wx0 = ix0 < 0 ? 0.f : (ix0 >= WC - 1 ? 1.f : __fsub_rn(1.f, fx));
        float wx1 = ix0 < 0 ? 1.f : (ix0 >= WC - 1 ? 0.f : fx);
        float t0 = __fmaf_rn(wx1, hm[y0 * WC + x1], __fmul_rn(wx0, hm[y0 * WC + x0]));
        float t1 = __fmaf_rn(wx1, hm[y1 * WC + x1], __fmul_rn(wx0, hm[y1 * WC + x0]));
        float rel = __fmaf_rn(wy1, t1, __fmul_rn(wy0, t0));

        float x = tile[lr + 2][c + 2];
        float lm = x;
        #pragma unroll
        for (int dy = 0; dy < 5; dy++)
            #pragma unroll
            for (int dx = 0; dx < 5; dx++)
                lm = fmaxf(lm, tile[lr + dy][c + dx]);
        float fs = (x == lm) ? __fmul_rn(x, rel) : 0.f;
        if (fs == 0.f) fs = 0.f;   // canonicalize -0
        int gid = b * NPIX + oy * W_IMG + ox;
        g_FS[gid] = fs;
        dout[OFF_H + gid] = fs;
        dout[OFF_R + gid] = rel;

        u32 bin = fkey(fs) >> 16;
        hist_add(g_hist[0][b], g_coarse[0][b], bin, 0xFFFFFFFFu);
    }
}

// threshold scan: parallel suffix-sum pick (identical integer results)
template <int L>
__global__ void k_scan() {
    int b = blockIdx.x;
    __shared__ u32 bufA[256], bufB[256];
    __shared__ int csel;
    __shared__ u32 krem2s;
    int t = threadIdx.x;
    u32 krem = g_krem[b];

    bufA[t] = g_coarse[L][b][t];
    __syncthreads();
    u32* cur = bufA; u32* nxt = bufB;
    #pragma unroll
    for (int off = 1; off < 256; off <<= 1) {
        u32 v = cur[t] + ((t + off < 256) ? cur[t + off] : 0u);
        __syncthreads();
        nxt[t] = v;
        __syncthreads();
        u32* tmp = cur; cur = nxt; nxt = tmp;
    }
    u32 sufN = (t == 255) ? 0u : cur[t + 1];
    if (cur[t] >= krem && sufN < krem) { csel = t; krem2s = krem - sufN; }
    __syncthreads();
    int cs = csel;
    u32 krem2 = krem2s;
    __syncthreads();

    bufA[t] = g_hist[L][b][cs * 256 + t];
    __syncthreads();
    cur = bufA; nxt = bufB;
    #pragma unroll
    for (int off = 1; off < 256; off <<= 1) {
        u32 v = cur[t] + ((t + off < 256) ? cur[t + off] : 0u);
        __syncthreads();
        nxt[t] = v;
        __syncthreads();
        u32* tmp = cur; cur = nxt; nxt = tmp;
    }
    u32 sufNf = (t == 255) ? 0u : cur[t + 1];
    if (cur[t] >= krem2 && sufNf < krem2) {
        g_krem[b] = krem2 - sufNf;
        g_prefix[b] = (g_prefix[b] << 16) | (u64)(u32)(cs * 256 + t);
    }
}

// full pass: definite -> g_sel; threshold-bin -> cand[0] + level-1 fine+coarse
__global__ void k_sel0() {
    int gid = blockIdx.x * blockDim.x + threadIdx.x;   // exact: 2*NPIX
    int b = gid / NPIX;
    u32 i = gid % NPIX;
    u64 key = ((u64)fkey(g_FS[gid]) << 32) | (u64)(0xFFFFFFFFu - i);
    u32 v0 = (u32)(g_prefix[b] & 0xFFFFu);
    u32 bin = (u32)(key >> 48);
    bool isDef = bin > v0, isCand = bin == v0;
    u32 md = __ballot_sync(0xFFFFFFFFu, isDef);
    if (isDef) {
        u32 pos = warp_append(&g_cnt[b], md);
        if (pos < K_TOP) g_sel[b][pos] = key;
    }
    u32 mc = __ballot_sync(0xFFFFFFFFu, isCand);
    if (isCand) {
        u32 pos = warp_append(&g_candn[b][0], mc);
        if (pos < CAND_MAX) g_cand[b][0][pos] = key;
        u32 bin2 = (u32)(key >> 32) & 0xFFFFu;
        hist_add(g_hist[1][b], g_coarse[1][b], bin2, mc);
    }
}

// level 1 over candidates: definite -> g_sel; exact-fkey ties -> cand[1]
__global__ void k_sel1() {
    int b = blockIdx.y;
    u32 N = g_candn[b][0];
    u32 v1 = (u32)(g_prefix[b] & 0xFFFFu);
    u32 total = (N + 255u) & ~255u;
    u32 t0 = blockIdx.x * blockDim.x + threadIdx.x;
    u32 stride = gridDim.x * blockDim.x;
    for (u32 t = t0; t < total; t += stride) {
        bool valid = t < N;
        u64 key = valid ? g_cand[b][0][t] : 0ull;
        u32 bin = (u32)(key >> 32) & 0xFFFFu;
        bool isDef = valid && (bin > v1);
        bool isTie = valid && (bin == v1);
        u32 md = __ballot_sync(0xFFFFFFFFu, isDef);
        if (isDef) {
            u32 pos = warp_append(&g_cnt[b], md);
            if (pos < K_TOP) g_sel[b][pos] = key;
        }
        u32 mt = __ballot_sync(0xFFFFFFFFu, isTie);
        if (isTie) {
            u32 pos = warp_append(&g_candn[b][1], mt);
            if (pos < CAND_MAX) g_cand[b][1][pos] = key;
        }
    }
}

// ties share exact fkey: take krem largest keys (= smallest indices) by rank
__global__ void k_tie() {
    int b = blockIdx.x;
    u32 N = g_candn[b][1];
    u32 need = g_krem[b];
    for (u32 t = threadIdx.x; t < N; t += 256) {
        u64 key = g_cand[b][1][t];
        u32 r = 0;
        for (u32 j = 0; j < N; j++) r += (g_cand[b][1][j] > key);
        if (r < need) {
            u32 pos = atomicAdd(&g_cnt[b], 1);
            if (pos < K_TOP) g_sel[b][pos] = key;
        }
    }
}

// rank-by-counting (keys unique): rank = #{keys greater}; emit kpts + topidx
__global__ void k_rank(float* __restrict__ dout) {
    int b = blockIdx.y;
    int i = blockIdx.x * 256 + threadIdx.x;
    u64 my = g_sel[b][i];
    __shared__ u64 tile[256];
    int r = 0;
    for (int t = 0; t < K_TOP; t += 256) {
        tile[threadIdx.x] = g_sel[b][t + threadIdx.x];
        __syncthreads();
        #pragma unroll 8
        for (int j = 0; j < 256; j++) r += (tile[j] > my);
        __syncthreads();
    }
    u32 idx = 0xFFFFFFFFu - (u32)my;
    g_topidx[b][r] = (int)idx;
    float x = (float)(idx % W_IMG), y = (float)(idx / W_IMG);
    dout[OFF_KPTS + (size_t)b * K_TOP * 2 + r * 2 + 0] = x;
    dout[OFF_KPTS + (size_t)b * K_TOP * 2 + r * 2 + 1] = y;
}

// grid-sample + renorm: 8 warps/block, one keypoint per warp (same per-warp math)
__global__ void k_desc() {
    int wrp = threadIdx.x >> 5, lane = threadIdx.x & 31;
    int k = blockIdx.x * 8 + wrp, b = blockIdx.y;
    int idx = g_topidx[b][k];
    float xf = (float)(idx % W_IMG), yf = (float)(idx / W_IMG);
    float gx = __fsub_rn(__fmul_rn(__fdiv_rn(xf, 639.f), 2.f), 1.f);
    float gy = __fsub_rn(__fmul_rn(__fdiv_rn(yf, 479.f), 2.f), 1.f);
    float ix = __fmul_rn(__fmul_rn(__fadd_rn(gx, 1.f), 0.5f), 79.f);
    float iy = __fmul_rn(__fmul_rn(__fadd_rn(gy, 1.f), 0.5f), 59.f);
    float ix0f = floorf(ix), iy0f = floorf(iy);
    float wx = __fsub_rn(ix, ix0f), wy = __fsub_rn(iy, iy0f);
    float omx = __fsub_rn(1.f, wx), omy = __fsub_rn(1.f, wy);
    int x0 = min(max((int)ix0f, 0), WC - 1), y0 = min(max((int)iy0f, 0), HC - 1);
    int x1 = min(x0 + 1, WC - 1), y1 = min(y0 + 1, HC - 1);
    int p00 = y0 * WC + x0, p01 = y0 * WC + x1, p10 = y1 * WC + x0, p11 = y1 * WC + x1;
    float v[2];
    #pragma unroll
    for (int t = 0; t < 2; t++) {
        int c = 2 * lane + t;
        const float* f = g_nf + ((size_t)b * CH + c) * NC;
        float t1 = __fmul_rn(__fmul_rn(f[p00], omx), omy);
        float t2 = __fmul_rn(__fmul_rn(f[p01], wx), omy);
        float t3 = __fmul_rn(__fmul_rn(f[p10], omx), wy);
        float t4 = __fmul_rn(__fmul_rn(f[p11], wx), wy);
        v[t] = __fadd_rn(__fadd_rn(__fadd_rn(t1, t2), t3), t4);
    }
    float pr = __fadd_rn(__fmul_rn(v[0], v[0]), __fmul_rn(v[1], v[1]));
    #pragma unroll
    for (int off = 16; off > 0; off >>= 1)
        pr = __fadd_rn(pr, __shfl_down_sync(0xFFFFFFFFu, pr, off));
    float n = fmaxf(__fsqrt_rn(__shfl_sync(0xFFFFFFFFu, pr, 0)), 1e-12f);
    g_desc[b][k][2 * lane + 0] = __fdiv_rn(v[0], n);
    g_desc[b][k][2 * lane + 1] = __fdiv_rn(v[1], n);
}

// sim: VALIDATED fp32 ascending-k chain per output; packed fma.rn.f32x2
// (two adjacent-column outputs per instruction; per-lane math bit-identical).
#define TS 128
__global__ void k_sim() {
    extern __shared__ float sh[];
    float* As = sh;             // [64][128] k-major
    float* Bs = sh + 64 * TS;   // [64][128] k-major
    int tid = threadIdx.x;
    int rb = blockIdx.y * TS;
    int cb = blockIdx.x * TS;
    const float4* d0 = (const float4*)&g_desc[0][0][0];
    const float4* d1 = (const float4*)&g_desc[1][0][0];
    for (int t = tid; t < TS * 16; t += 256) {
        int r = t >> 4, c4 = t & 15;
        float4 a = d0[(size_t)(rb + r) * 16 + c4];
        As[(c4 * 4 + 0) * TS + r] = a.x; As[(c4 * 4 + 1) * TS + r] = a.y;
        As[(c4 * 4 + 2) * TS + r] = a.z; As[(c4 * 4 + 3) * TS + r] = a.w;
        float4 bv = d1[(size_t)(cb + r) * 16 + c4];
        Bs[(c4 * 4 + 0) * TS + r] = bv.x; Bs[(c4 * 4 + 1) * TS + r] = bv.y;
        Bs[(c4 * 4 + 2) * TS + r] = bv.z; Bs[(c4 * 4 + 3) * TS + r] = bv.w;
    }
    __syncthreads();
    int tx = tid & 15, ty = tid >> 4;
    u64 acc2[8][4];                     // [row i][col-pair j2]: cols 2j2, 2j2+1
    #pragma unroll
    for (int i = 0; i < 8; i++)
        #pragma unroll
        for (int j2 = 0; j2 < 4; j2++) acc2[i][j2] = 0ull;
    #pragma unroll 4
    for (int kk = 0; kk < 64; kk++) {   // strictly ascending k
        const float* Ak = As + kk * TS;
        const float* Bk = Bs + kk * TS;
        float4 a0 = *(const float4*)(Ak + ty * 4);
        float4 a1 = *(const float4*)(Ak + 64 + ty * 4);
        float av[8] = {a0.x, a0.y, a0.z, a0.w, a1.x, a1.y, a1.z, a1.w};
        u64 ap[8];
        #pragma unroll
        for (int i = 0; i < 8; i++) PACKF2(ap[i], av[i], av[i]);
        u64 bp[4];
        bp[0] = *(const u64*)(Bk + tx * 4);
        bp[1] = *(const u64*)(Bk + tx * 4 + 2);
        bp[2] = *(const u64*)(Bk + 64 + tx * 4);
        bp[3] = *(const u64*)(Bk + 64 + tx * 4 + 2);
        #pragma unroll
        for (int i = 0; i < 8; i++)
            #pragma unroll
            for (int j2 = 0; j2 < 4; j2++)
                FMA2(acc2[i][j2], ap[i], bp[j2]);
    }
    __syncthreads();
    u64* rowP = (u64*)sh;
    u64* colP = rowP + TS;
    if (tid < TS) { rowP[tid] = 0ull; colP[tid] = 0ull; }
    __syncthreads();
    #pragma unroll
    for (int i = 0; i < 8; i++) {
        int lr = (i < 4) ? (ty * 4 + i) : (64 + ty * 4 + i - 4);
        u64 best = 0ull;
        #pragma unroll
        for (int j2 = 0; j2 < 4; j2++) {
            float lo, hi;
            UNPACKF2(lo, hi, acc2[i][j2]);
            int j = 2 * j2;
            int gc = cb + ((j < 4) ? (tx * 4 + j) : (64 + tx * 4 + j - 4));
            u64 k0 = ((u64)fkey(lo) << 32) | (u64)(0xFFFFFFFFu - (u32)gc);
            u64 k1 = ((u64)fkey(hi) << 32) | (u64)(0xFFFFFFFFu - (u32)(gc + 1));
            best = max(best, max(k0, k1));
        }
        atomicMax(&rowP[lr], best);
    }
    #pragma unroll
    for (int j2 = 0; j2 < 4; j2++) {
        int j = 2 * j2;
        int lc = (j < 4) ? (tx * 4 + j) : (64 + tx * 4 + j - 4);
        u64 b0 = 0ull, b1 = 0ull;
        #pragma unroll
        for (int i = 0; i < 8; i++) {
            float lo, hi;
            UNPACKF2(lo, hi, acc2[i][j2]);
            u32 gr = (u32)(rb + ((i < 4) ? (ty * 4 + i) : (64 + ty * 4 + i - 4)));
            b0 = max(b0, ((u64)fkey(lo) << 32) | (u64)(0xFFFFFFFFu - gr));
            b1 = max(b1, ((u64)fkey(hi) << 32) | (u64)(0xFFFFFFFFu - gr));
        }
        atomicMax(&colP[lc], b0);
        atomicMax(&colP[lc + 1], b1);
    }
    __syncthreads();
    if (tid < TS) {
        atomicMax(&g_rowP[rb + tid], rowP[tid]);
        atomicMax(&g_colP[cb + tid], colP[tid]);
    }
}

__global__ void k_final(float* __restrict__ dout) {
    int k = blockIdx.x * blockDim.x + threadIdx.x;   // exact: 4096
    u64 rp = g_rowP[k];
    float sc = unfkey((u32)(rp >> 32));
    u32 m01 = 0xFFFFFFFFu - (u32)rp;
    u64 cp = g_colP[m01];
    u32 m10 = 0xFFFFFFFFu - (u32)cp;
    bool valid = (m10 == (u32)k) && (sc > 0.1f);
    dout[OFF_MATCH + k] = (float)m01;
    dout[OFF_SCORE + k] = sc;
    dout[OFF_VALID + k] = valid ? 1.f : 0.f;
}

extern "C" void kernel_launch(void* const* d_in, const int* in_sizes, int n_in,
                              void* d_out, int out_size) {
    const float* feats   = (const float*)d_in[0];
    const float* logits  = (const float*)d_in[1];
    const float* heatmap = (const float*)d_in[2];
    float* out = (float*)d_out;

    cudaFuncSetAttribute(k_sim, cudaFuncAttributeMaxDynamicSharedMemorySize, 64 * TS * 2 * 4);

    k_prep<<<556, 256>>>(logits, feats);                 // prep + scratch init
    k_nms<<<dim3(W_IMG / 128, H_IMG / 16, 2), 256>>>(heatmap, out);
    k_scan<0><<<2, 256>>>();
    k_sel0<<<2 * NPIX / 256, 256>>>();
    k_scan<1><<<2, 256>>>();
    k_sel1<<<dim3(64, 2), 256>>>();
    k_tie<<<2, 256>>>();
    k_rank<<<dim3(K_TOP / 256, 2), 256>>>(out);
    k_desc<<<dim3(K_TOP / 8, 2), 256>>>();
    k_sim<<<dim3(K_TOP / TS, K_TOP / TS), 256, 64 * TS * 2 * 4>>>();
    k_final<<<K_TOP / 256, 256>>>(out);
}

// round 17
// speedup vs baseline: 1.1227x; 1.0137x over previous
#include <cuda_runtime.h>

typedef unsigned int u32;
typedef unsigned long long u64;

extern "C" __device__ float __nv_expf(float);   // libdevice expf (matches XLA)

#define K_TOP 4096
#define W_IMG 640
#define H_IMG 480
#define NPIX (W_IMG * H_IMG)      // 307200
#define WC 80
#define HC 60
#define NC (WC * HC)              // 4800
#define CH 64
#define CAND_MAX 320000

#define OFF_KPTS  0
#define OFF_MATCH 16384
#define OFF_SCORE 20480
#define OFF_VALID 24576
#define OFF_H     28672
#define OFF_R     643072

__device__ float g_Hs[2 * NPIX];
__device__ float g_FS[2 * NPIX];
__device__ float g_nf[2 * CH * NC];
__device__ u32   g_hist[2][2][65536];
__device__ u32   g_coarse[2][2][256];
__device__ u32   g_krem[2];
__device__ u32   g_cnt[2];
__device__ u32   g_candn[2][2];
__device__ u64   g_cand[2][2][CAND_MAX];
__device__ u64   g_sel[2][K_TOP];
__device__ int   g_topidx[2][K_TOP];
__device__ float g_desc[2][K_TOP][CH];
__device__ u64   g_rowP[K_TOP];
__device__ u64   g_colP[K_TOP];

__device__ __forceinline__ u32 fkey(float f) {
    u32 u = __float_as_uint(f);
    return (u >> 31) ? ~u : (u | 0x80000000u);
}
__device__ __forceinline__ float unfkey(u32 k) {
    return __uint_as_float((k >> 31) ? (k & 0x7FFFFFFFu) : ~k);
}

#define PACKF2(out, lo, hi) asm("mov.b64 %0, {%1, %2};" : "=l"(out) : "f"(lo), "f"(hi))
#define UNPACKF2(lo, hi, in) asm("mov.b64 {%0, %1}, %2;" : "=f"(lo), "=f"(hi) : "l"(in))
#define FMA2(acc, a, b) asm("fma.rn.f32x2 %0, %1, %2, %0;" : "+l"(acc) : "l"(a), "l"(b))

__device__ __forceinline__ u32 warp_append(u32* counter, u32 mask) {
    int lane = threadIdx.x & 31;
    u32 ldr = __ffs(mask) - 1;
    u32 base = 0;
    if ((u32)lane == ldr) base = atomicAdd(counter, __popc(mask));
    base = __shfl_sync(mask, base, ldr);
    return base + __popc(mask & ((1u << lane) - 1));
}

// aggregated histogram add for fine+coarse (mask = active lanes)
__device__ __forceinline__ void hist_add(u32* fine, u32* coarse, u32 bin, u32 mask) {
    u32 peers = __match_any_sync(mask, bin);
    if ((u32)(__ffs(peers) - 1) == (threadIdx.x & 31u))
        atomicAdd(&fine[bin], __popc(peers));
    u32 cbin = bin >> 8;
    u32 cpeers = __match_any_sync(mask, cbin);
    if ((u32)(__ffs(cpeers) - 1) == (threadIdx.x & 31u))
        atomicAdd(&coarse[cbin], __popc(cpeers));
}

// shared-memory suffix-sum threshold pick over coarse+fine histograms.
// Returns v (16-bit threshold bin) and writes *krem_out = remaining count.
// Identical integer results to the former k_scan kernels.
__device__ __forceinline__ u32 scan_pick(const u32* coarse, const u32* fine_base,
                                         u32 krem, u32* krem_out,
                                         u32* bufA, u32* bufB,
                                         int* s_csel, u32* s_krem2,
                                         u32* s_v, u32* s_kout) {
    int t = threadIdx.x;
    bufA[t] = coarse[t];
    __syncthreads();
    u32* cur = bufA; u32* nxt = bufB;
    #pragma unroll
    for (int off = 1; off < 256; off <<= 1) {
        u32 v = cur[t] + ((t + off < 256) ? cur[t + off] : 0u);
        __syncthreads();
        nxt[t] = v;
        __syncthreads();
        u32* tmp = cur; cur = nxt; nxt = tmp;
    }
    u32 sufN = (t == 255) ? 0u : cur[t + 1];
    if (cur[t] >= krem && sufN < krem) { *s_csel = t; *s_krem2 = krem - sufN; }
    __syncthreads();
    int cs = *s_csel;
    u32 krem2 = *s_krem2;
    __syncthreads();
    bufA[t] = fine_base[cs * 256 + t];
    __syncthreads();
    cur = bufA; nxt = bufB;
    #pragma unroll
    for (int off = 1; off < 256; off <<= 1) {
        u32 v = cur[t] + ((t + off < 256) ? cur[t + off] : 0u);
        __syncthreads();
        nxt[t] = v;
        __syncthreads();
        u32* tmp = cur; cur = nxt; nxt = tmp;
    }
    u32 sufNf = (t == 255) ? 0u : cur[t + 1];
    if (cur[t] >= krem2 && sufNf < krem2) {
        *s_v = (u32)(cs * 256 + t);
        *s_kout = krem2 - sufNf;
    }
    __syncthreads();
    *krem_out = *s_kout;
    return *s_v;
}

// fused: blocks 0..149 softmax+shuffle, 150..299 feats norm, 300..555 scratch init
__global__ void k_prep(const float* __restrict__ logits,
                       const float* __restrict__ feats) {
    __shared__ float sm[65 * 65 + 65];
    int blk = blockIdx.x;
    int lane = threadIdx.x & 31, wrp = threadIdx.x >> 5;
    if (blk >= 300) {
        int i = (blk - 300) * 256 + threadIdx.x;
        int st = 256 * 256;
        u32* h = &g_hist[0][0][0];
        for (int j = i; j < 2 * 2 * 65536; j += st) h[j] = 0;
        u32* c = &g_coarse[0][0][0];
        for (int j = i; j < 2 * 2 * 256; j += st) c[j] = 0;
        for (int j = i; j < K_TOP; j += st) { g_rowP[j] = 0ull; g_colP[j] = 0ull; }
        if (i < 2) {
            g_krem[i] = K_TOP; g_cnt[i] = 0;
            g_candn[i][0] = 0; g_candn[i][1] = 0;
        }
        return;
    }
    if (blk < 150) {
        int b = blk / 75;
        int cellbase = (blk % 75) * 64;
        const float* p = logits + (size_t)b * 65 * NC + cellbase;
        for (int i = threadIdx.x; i < 65 * 64; i += 256) {
            int ch = i >> 6, cl = i & 63;
            sm[ch * 65 + cl] = p[ch * NC + cl];
        }
        __syncthreads();
        float* out = g_Hs + (size_t)b * NPIX;
        #pragma unroll
        for (int s = 0; s < 8; s++) {
            int cell = wrp * 8 + s;
            float x0 = sm[lane * 65 + cell];
            float x1 = sm[(lane + 32) * 65 + cell];
            float x2 = (lane == 0) ? sm[64 * 65 + cell] : __int_as_float(0xff800000);
            float m = fmaxf(fmaxf(x0, x1), x2);
            #pragma unroll
            for (int off = 16; off > 0; off >>= 1)
                m = fmaxf(m, __shfl_xor_sync(0xFFFFFFFFu, m, off));
            float e0 = __nv_expf(__fsub_rn(x0, m));
            float e1 = __nv_expf(__fsub_rn(x1, m));
            float e2 = __nv_expf(__fsub_rn(x2, m));
            float partial = __fadd_rn(__fadd_rn(e0, e1), e2);
            #pragma unroll
            for (int off = 16; off > 0; off >>= 1)
                partial = __fadd_rn(partial, __shfl_down_sync(0xFFFFFFFFu, partial, off));
            float ssum = __shfl_sync(0xFFFFFFFFu, partial, 0);
            int gcell = cellbase + cell;
            int h = gcell / WC, w = gcell % WC;
            int c0 = lane, c1 = lane + 32;
            out[(h * 8 + (c0 >> 3)) * W_IMG + (w * 8 + (c0 & 7))] = __fdiv_rn(e0, ssum);
            out[(h * 8 + (c1 >> 3)) * W_IMG + (w * 8 + (c1 & 7))] = __fdiv_rn(e1, ssum);
        }
    } else {
        int blk2 = blk - 150;
        int b = blk2 / 75;
        int cellbase = (blk2 % 75) * 64;
        float* nrm = sm + 64 * 65;
        const float* f = feats + (size_t)b * CH * NC + cellbase;
        float* o = g_nf + (size_t)b * CH * NC + cellbase;
        for (int i = threadIdx.x; i < 64 * 64; i += 256) {
            int ch = i >> 6, cl = i & 63;
            sm[ch * 65 + cl] = f[ch * NC + cl];
        }
        __syncthreads();
        #pragma unroll
        for (int s = 0; s < 8; s++) {
            int cell = wrp * 8 + s;
            float x0 = sm[lane * 65 + cell];
            float x1 = sm[(lane + 32) * 65 + cell];
            float partial = __fadd_rn(__fmul_rn(x0, x0), __fmul_rn(x1, x1));
            #pragma unroll
            for (int off = 16; off > 0; off >>= 1)
                partial = __fadd_rn(partial, __shfl_down_sync(0xFFFFFFFFu, partial, off));
            if (lane == 0) nrm[cell] = fmaxf(__fsqrt_rn(partial), 1e-12f);
        }
        __syncthreads();
        for (int i = threadIdx.x; i < 64 * 64; i += 256) {
            int ch = i >> 6, cl = i & 63;
            o[ch * NC + cl] = __fdiv_rn(sm[ch * 65 + cl], nrm[cl]);
        }
    }
}

// 5x5 NMS, 2D tiles 128x16 outputs (halo 132x20) + bilinear + level-0 hist
__global__ void k_nms(const float* __restrict__ heatmap, float* __restrict__ dout) {
    __shared__ float tile[20][132];
    int b = blockIdx.z;
    int xbase = blockIdx.x * 128;
    int ybase = blockIdx.y * 16;
    int tid = threadIdx.x;                 // 256 threads
    const float* Hs = g_Hs + (size_t)b * NPIX;
    for (int i = tid; i < 20 * 132; i += 256) {
        int rr = i / 132, cc = i % 132;
        int row = ybase - 2 + rr, col = xbase - 2 + cc;
        float v = __int_as_float(0xff800000);
        if ((unsigned)row < H_IMG && (unsigned)col < W_IMG)
            v = Hs[row * W_IMG + col];
        tile[rr][cc] = v;
    }
    __syncthreads();
    int c = tid & 127, r0 = tid >> 7;      // 128 cols x 2 rows, 8 passes
    const float* hm = heatmap + (size_t)b * NC;
    #pragma unroll
    for (int pass = 0; pass < 8; pass++) {
        int lr = r0 + 2 * pass;            // local row 0..15
        int oy = ybase + lr, ox = xbase + c;

        float sy = __fsub_rn(__fmul_rn(__fadd_rn((float)oy, 0.5f), 0.125f), 0.5f);
        float sx = __fsub_rn(__fmul_rn(__fadd_rn((float)ox, 0.5f), 0.125f), 0.5f);
        int iy0 = (int)floorf(sy);
        int ix0 = (int)floorf(sx);
        float fy = __fsub_rn(sy, (float)iy0);
        float fx = __fsub_rn(sx, (float)ix0);
        int y0 = iy0 < 0 ? 0 : iy0;
        int y1 = iy0 >= HC - 1 ? HC - 1 : iy0 + 1;
        int x0 = ix0 < 0 ? 0 : ix0;
        int x1 = ix0 >= WC - 1 ? WC - 1 : ix0 + 1;
        float wy0 = iy0 < 0 ? 0.f : (iy0 >= HC - 1 ? 1.f : __fsub_rn(1.f, fy));
        float wy1 = iy0 < 0 ? 1.f : (iy0 >= HC - 1 ? 0.f : fy);
        float wx0 = ix0 < 0 ? 0.f : (ix0 >= WC - 1 ? 1.f : __fsub_rn(1.f, fx));
        float wx1 = ix0 < 0 ? 1.f : (ix0 >= WC - 1 ? 0.f : fx);
        float t0 = __fmaf_rn(wx1, hm[y0 * WC + x1], __fmul_rn(wx0, hm[y0 * WC + x0]));
        float t1 = __fmaf_rn(wx1, hm[y1 * WC + x1], __fmul_rn(wx0, hm[y1 * WC + x0]));
        float rel = __fmaf_rn(wy1, t1, __fmul_rn(wy0, t0));

        float x = tile[lr + 2][c + 2];
        float lm = x;
        #pragma unroll
        for (int dy = 0; dy < 5; dy++)
            #pragma unroll
            for (int dx = 0; dx < 5; dx++)
                lm = fmaxf(lm, tile[lr + dy][c + dx]);
        float fs = (x == lm) ? __fmul_rn(x, rel) : 0.f;
        if (fs == 0.f) fs = 0.f;   // canonicalize -0
        int gid = b * NPIX + oy * W_IMG + ox;
        g_FS[gid] = fs;
        dout[OFF_H + gid] = fs;
        dout[OFF_R + gid] = rel;

        u32 bin = fkey(fs) >> 16;
        hist_add(g_hist[0][b], g_coarse[0][b], bin, 0xFFFFFFFFu);
    }
}

// full pass with INLINE level-0 threshold (recomputed per block, identical pick):
// definite -> g_sel; threshold-bin -> cand[0] + level-1 fine+coarse hist
__global__ void k_sel0() {
    __shared__ u32 bufA[256], bufB[256];
    __shared__ int s_csel;
    __shared__ u32 s_krem2, s_v, s_kout;
    int blk = blockIdx.x;                  // 2400 blocks, 1200 per batch
    int b = blk / 1200;
    u32 krem1;
    u32 v0 = scan_pick(g_coarse[0][b], g_hist[0][b], K_TOP, &krem1,
                       bufA, bufB, &s_csel, &s_krem2, &s_v, &s_kout);
    if (threadIdx.x == 0) g_krem[b] = krem1;   // identical value from every block

    int gid = blk * 256 + threadIdx.x;     // exact: 2*NPIX
    u32 i = (u32)(gid - b * NPIX);
    u64 key = ((u64)fkey(g_FS[gid]) << 32) | (u64)(0xFFFFFFFFu - i);
    u32 bin = (u32)(key >> 48);
    bool isDef = bin > v0, isCand = bin == v0;
    u32 md = __ballot_sync(0xFFFFFFFFu, isDef);
    if (isDef) {
        u32 pos = warp_append(&g_cnt[b], md);
        if (pos < K_TOP) g_sel[b][pos] = key;
    }
    u32 mc = __ballot_sync(0xFFFFFFFFu, isCand);
    if (isCand) {
        u32 pos = warp_append(&g_candn[b][0], mc);
        if (pos < CAND_MAX) g_cand[b][0][pos] = key;
        u32 bin2 = (u32)(key >> 32) & 0xFFFFu;
        hist_add(g_hist[1][b], g_coarse[1][b], bin2, mc);
    }
}

// merged: level-1 scan + select + exact-fkey tie resolution. grid=2, block b = batch b.
__global__ void k_post() {
    __shared__ u32 bufA[256], bufB[256];
    __shared__ int s_csel;
    __shared__ u32 s_krem2, s_v, s_kout;
    int b = blockIdx.x;
    int t = threadIdx.x;
    u32 kremF;
    u32 v1 = scan_pick(g_coarse[1][b], g_hist[1][b], g_krem[b], &kremF,
                       bufA, bufB, &s_csel, &s_krem2, &s_v, &s_kout);

    // select over level-0 candidates
    u32 N = g_candn[b][0];
    u32 total = (N + 255u) & ~255u;
    for (u32 t2 = t; t2 < total; t2 += 256) {
        bool valid = t2 < N;
        u64 key = valid ? g_cand[b][0][t2] : 0ull;
        u32 bin = (u32)(key >> 32) & 0xFFFFu;
        bool isDef = valid && (bin > v1);
        bool isTie = valid && (bin == v1);
        u32 md = __ballot_sync(0xFFFFFFFFu, isDef);
        if (isDef) {
            u32 pos = warp_append(&g_cnt[b], md);
            if (pos < K_TOP) g_sel[b][pos] = key;
        }
        u32 mt = __ballot_sync(0xFFFFFFFFu, isTie);
        if (isTie) {
            u32 pos = warp_append(&g_candn[b][1], mt);
            if (pos < CAND_MAX) g_cand[b][1][pos] = key;
        }
    }
    __syncthreads();

    // tie resolution: ties share the exact fkey; take kremF largest (smallest idx)
    u32 N1 = g_candn[b][1];
    for (u32 tt = t; tt < N1; tt += 256) {
        u64 key = g_cand[b][1][tt];
        u32 r = 0;
        for (u32 j = 0; j < N1; j++) r += (g_cand[b][1][j] > key);
        if (r < kremF) {
            u32 pos = atomicAdd(&g_cnt[b], 1);
            if (pos < K_TOP) g_sel[b][pos] = key;
        }
    }
}

// rank-by-counting (keys unique): rank = #{keys greater}; emit kpts + topidx
__global__ void k_rank(float* __restrict__ dout) {
    int b = blockIdx.y;
    int i = blockIdx.x * 256 + threadIdx.x;
    u64 my = g_sel[b][i];
    __shared__ u64 tile[256];
    int r = 0;
    for (int t = 0; t < K_TOP; t += 256) {
        tile[threadIdx.x] = g_sel[b][t + threadIdx.x];
        __syncthreads();
        #pragma unroll 8
        for (int j = 0; j < 256; j++) r += (tile[j] > my);
        __syncthreads();
    }
    u32 idx = 0xFFFFFFFFu - (u32)my;
    g_topidx[b][r] = (int)idx;
    float x = (float)(idx % W_IMG), y = (float)(idx / W_IMG);
    dout[OFF_KPTS + (size_t)b * K_TOP * 2 + r * 2 + 0] = x;
    dout[OFF_KPTS + (size_t)b * K_TOP * 2 + r * 2 + 1] = y;
}

// grid-sample + renorm: 8 warps/block, one keypoint per warp (same per-warp math)
__global__ void k_desc() {
    int wrp = threadIdx.x >> 5, lane = threadIdx.x & 31;
    int k = blockIdx.x * 8 + wrp, b = blockIdx.y;
    int idx = g_topidx[b][k];
    float xf = (float)(idx % W_IMG), yf = (float)(idx / W_IMG);
    float gx = __fsub_rn(__fmul_rn(__fdiv_rn(xf, 639.f), 2.f), 1.f);
    float gy = __fsub_rn(__fmul_rn(__fdiv_rn(yf, 479.f), 2.f), 1.f);
    float ix = __fmul_rn(__fmul_rn(__fadd_rn(gx, 1.f), 0.5f), 79.f);
    float iy = __fmul_rn(__fmul_rn(__fadd_rn(gy, 1.f), 0.5f), 59.f);
    float ix0f = floorf(ix), iy0f = floorf(iy);
    float wx = __fsub_rn(ix, ix0f), wy = __fsub_rn(iy, iy0f);
    float omx = __fsub_rn(1.f, wx), omy = __fsub_rn(1.f, wy);
    int x0 = min(max((int)ix0f, 0), WC - 1), y0 = min(max((int)iy0f, 0), HC - 1);
    int x1 = min(x0 + 1, WC - 1), y1 = min(y0 + 1, HC - 1);
    int p00 = y0 * WC + x0, p01 = y0 * WC + x1, p10 = y1 * WC + x0, p11 = y1 * WC + x1;
    float v[2];
    #pragma unroll
    for (int t = 0; t < 2; t++) {
        int c = 2 * lane + t;
        const float* f = g_nf + ((size_t)b * CH + c) * NC;
        float t1 = __fmul_rn(__fmul_rn(f[p00], omx), omy);
        float t2 = __fmul_rn(__fmul_rn(f[p01], wx), omy);
        float t3 = __fmul_rn(__fmul_rn(f[p10], omx), wy);
        float t4 = __fmul_rn(__fmul_rn(f[p11], wx), wy);
        v[t] = __fadd_rn(__fadd_rn(__fadd_rn(t1, t2), t3), t4);
    }
    float pr = __fadd_rn(__fmul_rn(v[0], v[0]), __fmul_rn(v[1], v[1]));
    #pragma unroll
    for (int off = 16; off > 0; off >>= 1)
        pr = __fadd_rn(pr, __shfl_down_sync(0xFFFFFFFFu, pr, off));
    float n = fmaxf(__fsqrt_rn(__shfl_sync(0xFFFFFFFFu, pr, 0)), 1e-12f);
    g_desc[b][k][2 * lane + 0] = __fdiv_rn(v[0], n);
    g_desc[b][k][2 * lane + 1] = __fdiv_rn(v[1], n);
}

// sim: VALIDATED fp32 ascending-k chain per output; packed fma.rn.f32x2
// (two adjacent-column outputs per instruction; per-lane math bit-identical).
#define TS 128
__global__ void k_sim() {
    extern __shared__ float sh[];
    float* As = sh;             // [64][128] k-major
    float* Bs = sh + 64 * TS;   // [64][128] k-major
    int tid = threadIdx.x;
    int rb = blockIdx.y * TS;
    int cb = blockIdx.x * TS;
    const float4* d0 = (const float4*)&g_desc[0][0][0];
    const float4* d1 = (const float4*)&g_desc[1][0][0];
    for (int t = tid; t < TS * 16; t += 256) {
        int r = t >> 4, c4 = t & 15;
        float4 a = d0[(size_t)(rb + r) * 16 + c4];
        As[(c4 * 4 + 0) * TS + r] = a.x; As[(c4 * 4 + 1) * TS + r] = a.y;
        As[(c4 * 4 + 2) * TS + r] = a.z; As[(c4 * 4 + 3) * TS + r] = a.w;
        float4 bv = d1[(size_t)(cb + r) * 16 + c4];
        Bs[(c4 * 4 + 0) * TS + r] = bv.x; Bs[(c4 * 4 + 1) * TS + r] = bv.y;
        Bs[(c4 * 4 + 2) * TS + r] = bv.z; Bs[(c4 * 4 + 3) * TS + r] = bv.w;
    }
    __syncthreads();
    int tx = tid & 15, ty = tid >> 4;
    u64 acc2[8][4];                     // [row i][col-pair j2]: cols 2j2, 2j2+1
    #pragma unroll
    for (int i = 0; i < 8; i++)
        #pragma unroll
        for (int j2 = 0; j2 < 4; j2++) acc2[i][j2] = 0ull;
    #pragma unroll 4
    for (int kk = 0; kk < 64; kk++) {   // strictly ascending k
        const float* Ak = As + kk * TS;
        const float* Bk = Bs + kk * TS;
        float4 a0 = *(const float4*)(Ak + ty * 4);
        float4 a1 = *(const float4*)(Ak + 64 + ty * 4);
        float av[8] = {a0.x, a0.y, a0.z, a0.w, a1.x, a1.y, a1.z, a1.w};
        u64 ap[8];
        #pragma unroll
        for (int i = 0; i < 8; i++) PACKF2(ap[i], av[i], av[i]);
        u64 bp[4];
        bp[0] = *(const u64*)(Bk + tx * 4);
        bp[1] = *(const u64*)(Bk + tx * 4 + 2);
        bp[2] = *(const u64*)(Bk + 64 + tx * 4);
        bp[3] = *(const u64*)(Bk + 64 + tx * 4 + 2);
        #pragma unroll
        for (int i = 0; i < 8; i++)
            #pragma unroll
            for (int j2 = 0; j2 < 4; j2++)
                FMA2(acc2[i][j2], ap[i], bp[j2]);
    }
    __syncthreads();
    u64* rowP = (u64*)sh;
    u64* colP = rowP + TS;
    if (tid < TS) { rowP[tid] = 0ull; colP[tid] = 0ull; }
    __syncthreads();
    #pragma unroll
    for (int i = 0; i < 8; i++) {
        int lr = (i < 4) ? (ty * 4 + i) : (64 + ty * 4 + i - 4);
        u64 best = 0ull;
        #pragma unroll
        for (int j2 = 0; j2 < 4; j2++) {
            float lo, hi;
            UNPACKF2(lo, hi, acc2[i][j2]);
            int j = 2 * j2;
            int gc = cb + ((j < 4) ? (tx * 4 + j) : (64 + tx * 4 + j - 4));
            u64 k0 = ((u64)fkey(lo) << 32) | (u64)(0xFFFFFFFFu - (u32)gc);
            u64 k1 = ((u64)fkey(hi) << 32) | (u64)(0xFFFFFFFFu - (u32)(gc + 1));
            best = max(best, max(k0, k1));
        }
        atomicMax(&rowP[lr], best);
    }
    #pragma unroll
    for (int j2 = 0; j2 < 4; j2++) {
        int j = 2 * j2;
        int lc = (j < 4) ? (tx * 4 + j) : (64 + tx * 4 + j - 4);
        u64 b0 = 0ull, b1 = 0ull;
        #pragma unroll
        for (int i = 0; i < 8; i++) {
            float lo, hi;
            UNPACKF2(lo, hi, acc2[i][j2]);
            u32 gr = (u32)(rb + ((i < 4) ? (ty * 4 + i) : (64 + ty * 4 + i - 4)));
            b0 = max(b0, ((u64)fkey(lo) << 32) | (u64)(0xFFFFFFFFu - gr));
            b1 = max(b1, ((u64)fkey(hi) << 32) | (u64)(0xFFFFFFFFu - gr));
        }
        atomicMax(&colP[lc], b0);
        atomicMax(&colP[lc + 1], b1);
    }
    __syncthreads();
    if (tid < TS) {
        atomicMax(&g_rowP[rb + tid], rowP[tid]);
        atomicMax(&g_colP[cb + tid], colP[tid]);
    }
}

__global__ void k_final(float* __restrict__ dout) {
    int k = blockIdx.x * blockDim.x + threadIdx.x;   // exact: 4096
    u64 rp = g_rowP[k];
    float sc = unfkey((u32)(rp >> 32));
    u32 m01 = 0xFFFFFFFFu - (u32)rp;
    u64 cp = g_colP[m01];
    u32 m10 = 0xFFFFFFFFu - (u32)cp;
    bool valid = (m10 == (u32)k) && (sc > 0.1f);
    dout[OFF_MATCH + k] = (float)m01;
    dout[OFF_SCORE + k] = sc;
    dout[OFF_VALID + k] = valid ? 1.f : 0.f;
}

extern "C" void kernel_launch(void* const* d_in, const int* in_sizes, int n_in,
                              void* d_out, int out_size) {
    const float* feats   = (const float*)d_in[0];
    const float* logits  = (const float*)d_in[1];
    const float* heatmap = (const float*)d_in[2];
    float* out = (float*)d_out;

    cudaFuncSetAttribute(k_sim, cudaFuncAttributeMaxDynamicSharedMemorySize, 64 * TS * 2 * 4);

    k_prep<<<556, 256>>>(logits, feats);                 // prep + scratch init
    k_nms<<<dim3(W_IMG / 128, H_IMG / 16, 2), 256>>>(heatmap, out);
    k_sel0<<<2 * NPIX / 256, 256>>>();                   // inline level-0 scan
    k_post<<<2, 256>>>();                                // scan1 + sel1 + tie
    k_rank<<<dim3(K_TOP / 256, 2), 256>>>(out);
    k_desc<<<dim3(K_TOP / 8, 2), 256>>>();
    k_sim<<<dim3(K_TOP / TS, K_TOP / TS), 256, 64 * TS * 2 * 4>>>();
    k_final<<<K_TOP / 256, 256>>>(out);
}